// round 7
// baseline (speedup 1.0000x reference)
#include <cuda_runtime.h>

typedef unsigned long long ull;

// ---------------- problem dimensions ----------------
static constexpr int D1=41, H1=200, W1=176; static constexpr int N1=D1*H1*W1;   // 1,443,200
static constexpr int D2=21, H2=100, W2=88;  static constexpr int N2=D2*H2*W2;   // 184,800
static constexpr int D3=11, H3=50,  W3=44;  static constexpr int N3=D3*H3*W3;   // 24,200
static constexpr int D4=5,  H4=25,  W4=22;  static constexpr int N4=D4*H4*W4;   // 2,750
static constexpr int D5=2,  H5=25,  W5=22;  static constexpr int N5=D5*H5*W5;   // 1,100

// ---------------- static device scratch ----------------
__device__ __align__(16) float g_bufA[16 * N1];   // 92.4 MB ping
__device__ __align__(16) float g_bufB[16 * N1];   // 92.4 MB pong
__device__ float g_mask2[N2];
__device__ float g_mask3[N3];
__device__ float g_mask4[N4];
__device__ float g_mask5[N5];
__device__ __align__(16) float g_wr[710592];      // reordered weights, all 12 layers
__device__ int   g_list[N1];
__device__ int   g_cnt;

// weight region metadata (floats)
__device__ __constant__ int c_off[12] = {0, 1728, 8640, 22464, 50112, 77760, 133056,
                                         243648, 354240, 464832, 575424, 686016};
__device__ __constant__ int c_CI[12] = {4, 16, 16, 32, 32, 32, 64, 64, 64, 64, 64, 64};
__device__ __constant__ int c_CO[12] = {16, 16, 32, 32, 32, 64, 64, 64, 64, 64, 64, 128};
__device__ __constant__ int c_K3[12] = {27, 27, 27, 27, 27, 27, 27, 27, 27, 27, 27, 3};

struct WPtrs { const float* w[12]; };

// ---------------- f32x2 helpers ----------------
__device__ __forceinline__ ull f2_dup(float v) {
    ull r; asm("mov.b64 %0, {%1, %1};" : "=l"(r) : "f"(v)); return r;
}
__device__ __forceinline__ void f2_unpack(ull v, float& lo, float& hi) {
    asm("mov.b64 {%0, %1}, %2;" : "=f"(lo), "=f"(hi) : "l"(v));
}
#define FMA_F32X2(d, a, b, c) \
    asm("fma.rn.f32x2 %0, %1, %2, %3;" : "=l"(d) : "l"(a), "l"(b), "l"(c))

// ---------------- prelude kernels ----------------
__global__ void compact_kernel(const float* __restrict__ mask) {
    int i = blockIdx.x * blockDim.x + threadIdx.x;
    if (i < N1 && mask[i] != 0.0f) {
        int p = atomicAdd(&g_cnt, 1);
        g_list[p] = i;
    }
}

__global__ void prep_w_all(WPtrs p, float* __restrict__ wr) {
    int t = blockIdx.x * blockDim.x + threadIdx.x;
    if (t >= 710592) return;
    int L = 0;
    int base = 0;
    #pragma unroll
    for (int i = 0; i < 12; i++) {
        int n = c_CO[i] * c_CI[i] * c_K3[i];
        if (t >= base && t < base + n) { L = i; }
        base += n;
    }
    base = c_off[L];
    int local = t - base;
    int K3 = c_K3[L], CI = c_CI[L], CO = c_CO[L];
    int k  = local % K3;
    int r  = local / K3;
    int ci = r % CI;
    int co = r / CI;
    wr[base + (ci * K3 + k) * CO + co] = p.w[L][local];
}

__global__ void mask_pool_kernel(const float* __restrict__ mi, float* __restrict__ mo,
                                 int ID, int IH, int IW, int OD, int OH, int OW,
                                 int KD, int KH, int KW, int SD, int SH, int SW,
                                 int PD, int PH, int PW) {
    int o = blockIdx.x * blockDim.x + threadIdx.x;
    int n = OD * OH * OW;
    if (o >= n) return;
    int x = o % OW; int t = o / OW; int y = t % OH; int z = t / OH;
    float mx = 0.0f;
    for (int kz = 0; kz < KD; kz++) {
        int zi = z * SD - PD + kz; if ((unsigned)zi >= (unsigned)ID) continue;
        for (int ky = 0; ky < KH; ky++) {
            int yi = y * SH - PH + ky; if ((unsigned)yi >= (unsigned)IH) continue;
            for (int kx = 0; kx < KW; kx++) {
                int xi = x * SW - PW + kx; if ((unsigned)xi >= (unsigned)IW) continue;
                mx = fmaxf(mx, mi[(zi * IH + yi) * IW + xi]);
            }
        }
    }
    mo[o] = (mx > 0.0f) ? 1.0f : 0.0f;
}

// ---------------- sparse gather subm conv (3x3x3, stride1, pad1) ----------------
template<int CI, int CO>
__global__ void subm_gather_kernel(const float* __restrict__ in, const float* __restrict__ wr,
                                   const float* __restrict__ bn, float* __restrict__ out,
                                   int D, int H, int W) {
    const int q = threadIdx.x;       // [0, CO/4)
    const int n = g_cnt;
    for (int e = blockIdx.x * blockDim.y + threadIdx.y; e < n; e += gridDim.x * blockDim.y) {
        const int idx = g_list[e];
        const int x  = idx % W;
        const int zy = idx / W;
        const int y  = zy % H;
        const int z  = zy / H;

        float acc[4] = {0.f, 0.f, 0.f, 0.f};
        for (int ci = 0; ci < CI; ci++) {
            #pragma unroll
            for (int kz = 0; kz < 3; kz++) {
                int zi = z - 1 + kz; if ((unsigned)zi >= (unsigned)D) continue;
                #pragma unroll
                for (int ky = 0; ky < 3; ky++) {
                    int yi = y - 1 + ky; if ((unsigned)yi >= (unsigned)H) continue;
                    const float* __restrict__ prow = in + ((ci * D + zi) * (long)H + yi) * W + x;
                    const float* __restrict__ wrow = wr + ((ci * 3 + kz) * 3 + ky) * 3 * CO + 4 * q;
                    #pragma unroll
                    for (int kx = 0; kx < 3; kx++) {
                        int xi = x - 1 + kx;
                        float iv = ((unsigned)xi < (unsigned)W) ? __ldg(prow + kx - 1) : 0.0f;
                        float4 w4 = *reinterpret_cast<const float4*>(wrow + kx * CO);
                        acc[0] += iv * w4.x;
                        acc[1] += iv * w4.y;
                        acc[2] += iv * w4.z;
                        acc[3] += iv * w4.w;
                    }
                }
            }
        }
        #pragma unroll
        for (int j = 0; j < 4; j++) {
            int co = 4 * q + j;
            float g  = bn[co];
            float b  = bn[CO + co];
            float mu = bn[2 * CO + co];
            float vr = bn[3 * CO + co];
            float sc = g * rsqrtf(vr + 1e-3f);
            float sh = b - mu * sc;
            float val = fmaxf(acc[j] * sc + sh, 0.0f);
            out[((co * D + z) * (long)H + y) * W + x] = val;
        }
    }
}

// ---------------- dense tiled conv + BN + ReLU + mask (f32x2, CPT channels/thread) ----------------
// block = (CO/CPT, OW/V, YB): thread computes V consecutive-x voxels x CPT channels.
template<int CI, int CO, int CPT, int V, int YB,
         int KD, int KH, int KW, int SD, int SH, int SW, int PD, int PH, int PW>
__global__ void __launch_bounds__(352, 2)
conv_dense_kernel(const float* __restrict__ in, const float* __restrict__ wr,
                  const float* __restrict__ bn, const float* __restrict__ omask,
                  float* __restrict__ out,
                  int ID, int IH, int IW, int OD, int OH, int OW) {
    constexpr int NSEG = (V - 1) * SW + KW;
    constexpr int NP = CPT / 2;        // f32x2 pairs
    constexpr int NW = CPT / 4;        // float4 weight loads per kx
    const int q   = threadIdx.x;       // [0, CO/CPT)
    const int co0 = q * CPT;
    const int x0  = threadIdx.y * V;
    const int y   = blockIdx.y * YB + threadIdx.z;
    const int z   = blockIdx.z;
    if (y >= OH || x0 >= OW) return;

    float m[V];
    const int obase = (z * OH + y) * OW;
    float msum = 0.0f;
    #pragma unroll
    for (int v = 0; v < V; v++) {
        m[v] = (x0 + v < OW) ? omask[obase + x0 + v] : 0.0f;
        msum += m[v];
    }
    const bool any = msum > 0.0f;

    ull acc[V][NP];
    #pragma unroll
    for (int v = 0; v < V; v++)
        #pragma unroll
        for (int j = 0; j < NP; j++) acc[v][j] = 0ull;

    if (any) {
        const int zi0 = z * SD - PD;
        const int yi0 = y * SH - PH;
        const int xi0 = x0 * SW - PW;
        for (int ci = 0; ci < CI; ci++) {
            #pragma unroll
            for (int kz = 0; kz < KD; kz++) {
                int zi = zi0 + kz; if ((unsigned)zi >= (unsigned)ID) continue;
                #pragma unroll
                for (int ky = 0; ky < KH; ky++) {
                    int yi = yi0 + ky; if ((unsigned)yi >= (unsigned)IH) continue;
                    const float* __restrict__ prow = in + ((ci * ID + zi) * (long)IH + yi) * IW;
                    ull iv2[NSEG];
                    #pragma unroll
                    for (int s = 0; s < NSEG; s++) {
                        int xi = xi0 + s;
                        float f = ((unsigned)xi < (unsigned)IW) ? __ldg(prow + xi) : 0.0f;
                        iv2[s] = f2_dup(f);
                    }
                    const float* __restrict__ wrow =
                        wr + ((ci * KD + kz) * KH + ky) * KW * CO + co0;
                    #pragma unroll
                    for (int kx = 0; kx < KW; kx++) {
                        union { float4 f; ull u[2]; } wu[NW];
                        #pragma unroll
                        for (int wld = 0; wld < NW; wld++)
                            wu[wld].f = *reinterpret_cast<const float4*>(wrow + kx * CO + 4 * wld);
                        #pragma unroll
                        for (int v = 0; v < V; v++) {
                            ull iv = iv2[v * SW + kx];
                            #pragma unroll
                            for (int wld = 0; wld < NW; wld++) {
                                FMA_F32X2(acc[v][2 * wld + 0], iv, wu[wld].u[0], acc[v][2 * wld + 0]);
                                FMA_F32X2(acc[v][2 * wld + 1], iv, wu[wld].u[1], acc[v][2 * wld + 1]);
                            }
                        }
                    }
                }
            }
        }
    }

    #pragma unroll
    for (int j = 0; j < NP; j++) {
        int ca = co0 + 2 * j, cb = ca + 1;
        float sca = bn[ca] * rsqrtf(bn[3 * CO + ca] + 1e-3f);
        float sha = bn[CO + ca] - bn[2 * CO + ca] * sca;
        float scb = bn[cb] * rsqrtf(bn[3 * CO + cb] + 1e-3f);
        float shb = bn[CO + cb] - bn[2 * CO + cb] * scb;
        #pragma unroll
        for (int v = 0; v < V; v++) {
            int x = x0 + v;
            if (x < OW) {
                float a0, a1; f2_unpack(acc[v][j], a0, a1);
                bool act = m[v] > 0.0f;
                out[((ca * OD + z) * (long)OH + y) * OW + x] =
                    act ? fmaxf(fmaf(a0, sca, sha), 0.0f) : 0.0f;
                out[((cb * OD + z) * (long)OH + y) * OW + x] =
                    act ? fmaxf(fmaf(a1, scb, shb), 0.0f) : 0.0f;
            }
        }
    }
}

// ---------------- launch ----------------
extern "C" void kernel_launch(void* const* d_in, const int* in_sizes, int n_in,
                              void* d_out, int out_size) {
    const float* x    = (const float*)d_in[0];
    const float* mask = (const float*)d_in[1];
    WPtrs wp;
    const float* B_[12];
    for (int i = 0; i < 12; i++) {
        wp.w[i] = (const float*)d_in[2 + 2 * i];
        B_[i]   = (const float*)d_in[3 + 2 * i];
    }
    float* out = (float*)d_out;

    float *bufA, *bufB, *wr, *m2, *m3, *m4, *m5;
    int* cntp;
    cudaGetSymbolAddress((void**)&bufA, g_bufA);
    cudaGetSymbolAddress((void**)&bufB, g_bufB);
    cudaGetSymbolAddress((void**)&wr,   g_wr);
    cudaGetSymbolAddress((void**)&m2,   g_mask2);
    cudaGetSymbolAddress((void**)&m3,   g_mask3);
    cudaGetSymbolAddress((void**)&m4,   g_mask4);
    cudaGetSymbolAddress((void**)&m5,   g_mask5);
    cudaGetSymbolAddress((void**)&cntp, g_cnt);

    static const int off[12] = {0, 1728, 8640, 22464, 50112, 77760, 133056,
                                243648, 354240, 464832, 575424, 686016};

    cudaMemsetAsync(cntp, 0, sizeof(int), 0);
    cudaMemsetAsync(bufA, 0, sizeof(float) * 16 * (size_t)N1, 0);
    cudaMemsetAsync(bufB, 0, sizeof(float) * 16 * (size_t)N1, 0);

    prep_w_all<<<(710592 + 255) / 256, 256>>>(wp, wr);
    compact_kernel<<<(N1 + 255) / 256, 256>>>(mask);

    subm_gather_kernel<4, 16><<<1024, dim3(4, 32)>>>(x, wr + off[0], B_[0], bufA, D1, H1, W1);
    subm_gather_kernel<16, 16><<<1024, dim3(4, 32)>>>(bufA, wr + off[1], B_[1], bufB, D1, H1, W1);

    // launch 4: mask2 ; launch 5: L2 dense conv (ncu -s 5 lands here)
    mask_pool_kernel<<<(N2 + 255) / 256, 256>>>(mask, m2, D1, H1, W1, D2, H2, W2,
                                                3, 3, 3, 2, 2, 2, 1, 1, 1);
    // stage 2: CO=32, CPT=8 -> q in [0,4); block (4,22,4)=352, grid (1,25,21)
    conv_dense_kernel<16, 32, 8, 4, 4, 3, 3, 3, 2, 2, 2, 1, 1, 1>
        <<<dim3(1, (H2 + 3) / 4, D2), dim3(4, 22, 4)>>>(bufB, wr + off[2], B_[2], m2, bufA,
                                                        D1, H1, W1, D2, H2, W2);
    conv_dense_kernel<32, 32, 8, 4, 4, 3, 3, 3, 1, 1, 1, 1, 1, 1>
        <<<dim3(1, (H2 + 3) / 4, D2), dim3(4, 22, 4)>>>(bufA, wr + off[3], B_[3], m2, bufB,
                                                        D2, H2, W2, D2, H2, W2);
    conv_dense_kernel<32, 32, 8, 4, 4, 3, 3, 3, 1, 1, 1, 1, 1, 1>
        <<<dim3(1, (H2 + 3) / 4, D2), dim3(4, 22, 4)>>>(bufB, wr + off[4], B_[4], m2, bufA,
                                                        D2, H2, W2, D2, H2, W2);

    mask_pool_kernel<<<(N3 + 255) / 256, 256>>>(m2, m3, D2, H2, W2, D3, H3, W3,
                                                3, 3, 3, 2, 2, 2, 1, 1, 1);
    // stage 3: CO=64, CPT=8 -> q in [0,8); block (8,11,4)=352, grid (1,13,11)
    conv_dense_kernel<32, 64, 8, 4, 4, 3, 3, 3, 2, 2, 2, 1, 1, 1>
        <<<dim3(1, (H3 + 3) / 4, D3), dim3(8, 11, 4)>>>(bufA, wr + off[5], B_[5], m3, bufB,
                                                        D2, H2, W2, D3, H3, W3);
    conv_dense_kernel<64, 64, 8, 4, 4, 3, 3, 3, 1, 1, 1, 1, 1, 1>
        <<<dim3(1, (H3 + 3) / 4, D3), dim3(8, 11, 4)>>>(bufB, wr + off[6], B_[6], m3, bufA,
                                                        D3, H3, W3, D3, H3, W3);
    conv_dense_kernel<64, 64, 8, 4, 4, 3, 3, 3, 1, 1, 1, 1, 1, 1>
        <<<dim3(1, (H3 + 3) / 4, D3), dim3(8, 11, 4)>>>(bufA, wr + off[7], B_[7], m3, bufB,
                                                        D3, H3, W3, D3, H3, W3);

    mask_pool_kernel<<<(N4 + 255) / 256, 256>>>(m3, m4, D3, H3, W3, D4, H4, W4,
                                                3, 3, 3, 2, 2, 2, 0, 1, 1);
    // stage 4: CO=64, CPT=8, V=2; block (8,11,4)=352, grid (1,7,5)
    conv_dense_kernel<64, 64, 8, 2, 4, 3, 3, 3, 2, 2, 2, 0, 1, 1>
        <<<dim3(1, (H4 + 3) / 4, D4), dim3(8, 11, 4)>>>(bufB, wr + off[8], B_[8], m4, bufA,
                                                        D3, H3, W3, D4, H4, W4);
    conv_dense_kernel<64, 64, 8, 2, 4, 3, 3, 3, 1, 1, 1, 1, 1, 1>
        <<<dim3(1, (H4 + 3) / 4, D4), dim3(8, 11, 4)>>>(bufA, wr + off[9], B_[9], m4, bufB,
                                                        D4, H4, W4, D4, H4, W4);
    conv_dense_kernel<64, 64, 8, 2, 4, 3, 3, 3, 1, 1, 1, 1, 1, 1>
        <<<dim3(1, (H4 + 3) / 4, D4), dim3(8, 11, 4)>>>(bufB, wr + off[10], B_[10], m4, bufA,
                                                        D4, H4, W4, D4, H4, W4);

    mask_pool_kernel<<<(N5 + 255) / 256, 256>>>(m4, m5, D4, H4, W4, D5, H5, W5,
                                                3, 1, 1, 2, 1, 1, 0, 0, 0);
    // L11: CO=128, CPT=8 -> q in [0,16); block (16,11,2)=352, grid (1,13,2)
    conv_dense_kernel<64, 128, 8, 2, 2, 3, 1, 1, 2, 1, 1, 0, 0, 0>
        <<<dim3(1, (H5 + 1) / 2, D5), dim3(16, 11, 2)>>>(bufA, wr + off[11], B_[11], m5, out,
                                                         D4, H4, W4, D5, H5, W5);
}

// round 8
// speedup vs baseline: 1.4372x; 1.4372x over previous
#include <cuda_runtime.h>

typedef unsigned long long ull;

// ---------------- problem dimensions ----------------
static constexpr int D1=41, H1=200, W1=176; static constexpr int N1=D1*H1*W1;   // 1,443,200
static constexpr int D2=21, H2=100, W2=88;  static constexpr int N2=D2*H2*W2;   // 184,800
static constexpr int D3=11, H3=50,  W3=44;  static constexpr int N3=D3*H3*W3;   // 24,200
static constexpr int D4=5,  H4=25,  W4=22;  static constexpr int N4=D4*H4*W4;   // 2,750
static constexpr int D5=2,  H5=25,  W5=22;  static constexpr int N5=D5*H5*W5;   // 1,100

// ---------------- static device scratch ----------------
__device__ __align__(16) float g_bufA[16 * N1];   // 92.4 MB ping
__device__ __align__(16) float g_bufB[16 * N1];   // 92.4 MB pong
__device__ float g_mask2[N2];
__device__ float g_mask3[N3];
__device__ float g_mask4[N4];
__device__ float g_mask5[N5];
__device__ __align__(16) float g_wr[710592];      // reordered weights, all 12 layers
__device__ int   g_list[N1];
__device__ int   g_cnt;

// weight region metadata (floats)
__device__ __constant__ int c_off[12] = {0, 1728, 8640, 22464, 50112, 77760, 133056,
                                         243648, 354240, 464832, 575424, 686016};
__device__ __constant__ int c_CI[12] = {4, 16, 16, 32, 32, 32, 64, 64, 64, 64, 64, 64};
__device__ __constant__ int c_CO[12] = {16, 16, 32, 32, 32, 64, 64, 64, 64, 64, 64, 128};
__device__ __constant__ int c_K3[12] = {27, 27, 27, 27, 27, 27, 27, 27, 27, 27, 27, 3};

struct WPtrs { const float* w[12]; };

// ---------------- f32x2 + cp.async helpers ----------------
__device__ __forceinline__ ull f2_dup(float v) {
    ull r; asm("mov.b64 %0, {%1, %1};" : "=l"(r) : "f"(v)); return r;
}
__device__ __forceinline__ void f2_unpack(ull v, float& lo, float& hi) {
    asm("mov.b64 {%0, %1}, %2;" : "=f"(lo), "=f"(hi) : "l"(v));
}
#define FMA_F32X2(d, a, b, c) \
    asm("fma.rn.f32x2 %0, %1, %2, %3;" : "=l"(d) : "l"(a), "l"(b), "l"(c))

__device__ __forceinline__ void cp4(float* dst, const float* src) {
    unsigned d = (unsigned)__cvta_generic_to_shared(dst);
    asm volatile("cp.async.ca.shared.global [%0], [%1], 4;" :: "r"(d), "l"(src));
}
#define CP_COMMIT() asm volatile("cp.async.commit_group;" ::: "memory")
#define CP_WAIT1()  asm volatile("cp.async.wait_group 1;"  ::: "memory")

// ---------------- prelude kernels ----------------
__global__ void compact_kernel(const float* __restrict__ mask) {
    int i = blockIdx.x * blockDim.x + threadIdx.x;
    if (i < N1 && mask[i] != 0.0f) {
        int p = atomicAdd(&g_cnt, 1);
        g_list[p] = i;
    }
}

__global__ void prep_w_all(WPtrs p, float* __restrict__ wr) {
    int t = blockIdx.x * blockDim.x + threadIdx.x;
    if (t >= 710592) return;
    int L = 0;
    int base = 0;
    #pragma unroll
    for (int i = 0; i < 12; i++) {
        int n = c_CO[i] * c_CI[i] * c_K3[i];
        if (t >= base && t < base + n) { L = i; }
        base += n;
    }
    base = c_off[L];
    int local = t - base;
    int K3 = c_K3[L], CI = c_CI[L], CO = c_CO[L];
    int k  = local % K3;
    int r  = local / K3;
    int ci = r % CI;
    int co = r / CI;
    wr[base + (ci * K3 + k) * CO + co] = p.w[L][local];
}

__global__ void mask_pool_kernel(const float* __restrict__ mi, float* __restrict__ mo,
                                 int ID, int IH, int IW, int OD, int OH, int OW,
                                 int KD, int KH, int KW, int SD, int SH, int SW,
                                 int PD, int PH, int PW) {
    int o = blockIdx.x * blockDim.x + threadIdx.x;
    int n = OD * OH * OW;
    if (o >= n) return;
    int x = o % OW; int t = o / OW; int y = t % OH; int z = t / OH;
    float mx = 0.0f;
    for (int kz = 0; kz < KD; kz++) {
        int zi = z * SD - PD + kz; if ((unsigned)zi >= (unsigned)ID) continue;
        for (int ky = 0; ky < KH; ky++) {
            int yi = y * SH - PH + ky; if ((unsigned)yi >= (unsigned)IH) continue;
            for (int kx = 0; kx < KW; kx++) {
                int xi = x * SW - PW + kx; if ((unsigned)xi >= (unsigned)IW) continue;
                mx = fmaxf(mx, mi[(zi * IH + yi) * IW + xi]);
            }
        }
    }
    mo[o] = (mx > 0.0f) ? 1.0f : 0.0f;
}

// ---------------- sparse gather subm conv (3x3x3, stride1, pad1) ----------------
template<int CI, int CO>
__global__ void subm_gather_kernel(const float* __restrict__ in, const float* __restrict__ wr,
                                   const float* __restrict__ bn, float* __restrict__ out,
                                   int D, int H, int W) {
    const int q = threadIdx.x;       // [0, CO/4)
    const int n = g_cnt;
    for (int e = blockIdx.x * blockDim.y + threadIdx.y; e < n; e += gridDim.x * blockDim.y) {
        const int idx = g_list[e];
        const int x  = idx % W;
        const int zy = idx / W;
        const int y  = zy % H;
        const int z  = zy / H;

        float acc[4] = {0.f, 0.f, 0.f, 0.f};
        for (int ci = 0; ci < CI; ci++) {
            #pragma unroll
            for (int kz = 0; kz < 3; kz++) {
                int zi = z - 1 + kz; if ((unsigned)zi >= (unsigned)D) continue;
                #pragma unroll
                for (int ky = 0; ky < 3; ky++) {
                    int yi = y - 1 + ky; if ((unsigned)yi >= (unsigned)H) continue;
                    const float* __restrict__ prow = in + ((ci * D + zi) * (long)H + yi) * W + x;
                    const float* __restrict__ wrow = wr + ((ci * 3 + kz) * 3 + ky) * 3 * CO + 4 * q;
                    #pragma unroll
                    for (int kx = 0; kx < 3; kx++) {
                        int xi = x - 1 + kx;
                        float iv = ((unsigned)xi < (unsigned)W) ? __ldg(prow + kx - 1) : 0.0f;
                        float4 w4 = *reinterpret_cast<const float4*>(wrow + kx * CO);
                        acc[0] += iv * w4.x;
                        acc[1] += iv * w4.y;
                        acc[2] += iv * w4.z;
                        acc[3] += iv * w4.w;
                    }
                }
            }
        }
        #pragma unroll
        for (int j = 0; j < 4; j++) {
            int co = 4 * q + j;
            float g  = bn[co];
            float b  = bn[CO + co];
            float mu = bn[2 * CO + co];
            float vr = bn[3 * CO + co];
            float sc = g * rsqrtf(vr + 1e-3f);
            float sh = b - mu * sc;
            float val = fmaxf(acc[j] * sc + sh, 0.0f);
            out[((co * D + z) * (long)H + y) * W + x] = val;
        }
    }
}

// ---------------- dense conv: cp.async smem pipeline + f32x2 MACs ----------------
// block = (CO/4, OWT/V, YB); block covers one full x-row and YB y-rows.
// Per-CI receptive-field slice staged in smem (2-deep ring, cp.async).
template<int CI, int CO, int V, int YB, int OWT, int NT,
         int KD, int KH, int KW, int SD, int SH, int SW, int PD, int PH, int PW>
__global__ void __launch_bounds__(NT, 2)
conv_smem_kernel(const float* __restrict__ in, const float* __restrict__ wr,
                 const float* __restrict__ bn, const float* __restrict__ omask,
                 float* __restrict__ out,
                 int ID, int IH, int IW, int OD, int OH, int OW) {
    constexpr int NSEG = (V - 1) * SW + KW;
    constexpr int SMH  = (YB - 1) * SH + KH;           // rows per z-plane
    constexpr int SMW  = (OWT - 1) * SW + KW;          // floats per row
    constexpr int SMTOT = KD * SMH * SMW;

    __shared__ float sm[2][SMTOT];

    const int q   = threadIdx.x;                        // channel quad
    const int tz  = threadIdx.z;
    const int x0  = threadIdx.y * V;
    const int y   = blockIdx.y * YB + tz;
    const int z   = blockIdx.z;
    const int tid = threadIdx.x + blockDim.x * (threadIdx.y + blockDim.y * threadIdx.z);

    const bool active = (y < OH);

    // CI-invariant source geometry for the loader
    const int zi_base = z * SD - PD;
    const int yi_base = blockIdx.y * YB * SH - PH;

    // zero both buffers once (OOB cells stay zero forever)
    for (int i = tid; i < 2 * SMTOT; i += NT)
        (&sm[0][0])[i] = 0.0f;
    __syncthreads();

    // masks
    float m[V];
    float msum = 0.0f;
    if (active) {
        const int obase = (z * OH + y) * OW;
        #pragma unroll
        for (int v = 0; v < V; v++) {
            m[v] = (x0 + v < OW) ? omask[obase + x0 + v] : 0.0f;
            msum += m[v];
        }
    } else {
        #pragma unroll
        for (int v = 0; v < V; v++) m[v] = 0.0f;
    }
    const bool any = active && (msum > 0.0f);

    ull acc[V][2];
    #pragma unroll
    for (int v = 0; v < V; v++) { acc[v][0] = 0ull; acc[v][1] = 0ull; }

    // loader lambda: fetch CI-slice `ci` into buffer b
    auto load_ci = [&](int ci, int b) {
        const float* __restrict__ base = in + (long)ci * ID * IH * IW;
        for (int i = tid; i < SMTOT; i += NT) {
            int s  = i % SMW;
            int t2 = i / SMW;
            int r  = t2 % SMH;
            int kz = t2 / SMH;
            int zi = zi_base + kz;
            int yi = yi_base + r;
            int xi = s - PW;
            if ((unsigned)zi < (unsigned)ID && (unsigned)yi < (unsigned)IH &&
                (unsigned)xi < (unsigned)IW)
                cp4(&sm[b][i], base + ((long)zi * IH + yi) * IW + xi);
        }
    };

    // prologue: stage ci=0
    load_ci(0, 0);
    CP_COMMIT();

    for (int ci = 0; ci < CI; ci++) {
        if (ci + 1 < CI) load_ci(ci + 1, (ci + 1) & 1);
        CP_COMMIT();
        CP_WAIT1();
        __syncthreads();

        if (any) {
            const float* __restrict__ smb = sm[ci & 1];
            const float* __restrict__ wci = wr + ci * (KD * KH * KW * CO) + 4 * q;
            #pragma unroll
            for (int kz = 0; kz < KD; kz++) {
                #pragma unroll
                for (int ky = 0; ky < KH; ky++) {
                    const float* __restrict__ row =
                        smb + ((kz * SMH) + tz * SH + ky) * SMW + x0 * SW;
                    ull iv2[NSEG];
                    #pragma unroll
                    for (int s = 0; s < NSEG; s++)
                        iv2[s] = f2_dup(row[s]);
                    const float* __restrict__ wrow = wci + (kz * KH + ky) * KW * CO;
                    #pragma unroll
                    for (int kx = 0; kx < KW; kx++) {
                        union { float4 f; ull u[2]; } wu;
                        wu.f = *reinterpret_cast<const float4*>(wrow + kx * CO);
                        #pragma unroll
                        for (int v = 0; v < V; v++) {
                            ull iv = iv2[v * SW + kx];
                            FMA_F32X2(acc[v][0], iv, wu.u[0], acc[v][0]);
                            FMA_F32X2(acc[v][1], iv, wu.u[1], acc[v][1]);
                        }
                    }
                }
            }
        }
        __syncthreads();
    }

    if (active) {
        #pragma unroll
        for (int j = 0; j < 2; j++) {
            int ca = 4 * q + 2 * j, cb = ca + 1;
            float sca = bn[ca] * rsqrtf(bn[3 * CO + ca] + 1e-3f);
            float sha = bn[CO + ca] - bn[2 * CO + ca] * sca;
            float scb = bn[cb] * rsqrtf(bn[3 * CO + cb] + 1e-3f);
            float shb = bn[CO + cb] - bn[2 * CO + cb] * scb;
            #pragma unroll
            for (int v = 0; v < V; v++) {
                int x = x0 + v;
                if (x < OW) {
                    float a0, a1; f2_unpack(acc[v][j], a0, a1);
                    bool act = m[v] > 0.0f;
                    out[((ca * OD + z) * (long)OH + y) * OW + x] =
                        act ? fmaxf(fmaf(a0, sca, sha), 0.0f) : 0.0f;
                    out[((cb * OD + z) * (long)OH + y) * OW + x] =
                        act ? fmaxf(fmaf(a1, scb, shb), 0.0f) : 0.0f;
                }
            }
        }
    }
}

// ---------------- launch ----------------
extern "C" void kernel_launch(void* const* d_in, const int* in_sizes, int n_in,
                              void* d_out, int out_size) {
    const float* x    = (const float*)d_in[0];
    const float* mask = (const float*)d_in[1];
    WPtrs wp;
    const float* B_[12];
    for (int i = 0; i < 12; i++) {
        wp.w[i] = (const float*)d_in[2 + 2 * i];
        B_[i]   = (const float*)d_in[3 + 2 * i];
    }
    float* out = (float*)d_out;

    float *bufA, *bufB, *wr, *m2, *m3, *m4, *m5;
    int* cntp;
    cudaGetSymbolAddress((void**)&bufA, g_bufA);
    cudaGetSymbolAddress((void**)&bufB, g_bufB);
    cudaGetSymbolAddress((void**)&wr,   g_wr);
    cudaGetSymbolAddress((void**)&m2,   g_mask2);
    cudaGetSymbolAddress((void**)&m3,   g_mask3);
    cudaGetSymbolAddress((void**)&m4,   g_mask4);
    cudaGetSymbolAddress((void**)&m5,   g_mask5);
    cudaGetSymbolAddress((void**)&cntp, g_cnt);

    static const int off[12] = {0, 1728, 8640, 22464, 50112, 77760, 133056,
                                243648, 354240, 464832, 575424, 686016};

    cudaMemsetAsync(cntp, 0, sizeof(int), 0);
    cudaMemsetAsync(bufA, 0, sizeof(float) * 16 * (size_t)N1, 0);
    cudaMemsetAsync(bufB, 0, sizeof(float) * 16 * (size_t)N1, 0);

    prep_w_all<<<(710592 + 255) / 256, 256>>>(wp, wr);
    compact_kernel<<<(N1 + 255) / 256, 256>>>(mask);

    subm_gather_kernel<4, 16><<<1024, dim3(4, 32)>>>(x, wr + off[0], B_[0], bufA, D1, H1, W1);
    subm_gather_kernel<16, 16><<<1024, dim3(4, 32)>>>(bufA, wr + off[1], B_[1], bufB, D1, H1, W1);

    // launch 4: mask2 ; launch 5: L2 dense conv
    mask_pool_kernel<<<(N2 + 255) / 256, 256>>>(mask, m2, D1, H1, W1, D2, H2, W2,
                                                3, 3, 3, 2, 2, 2, 1, 1, 1);
    // stage 2 (OW=88): block (8,22,2)=352
    conv_smem_kernel<16, 32, 4, 2, 88, 352, 3, 3, 3, 2, 2, 2, 1, 1, 1>
        <<<dim3(1, H2 / 2, D2), dim3(8, 22, 2)>>>(bufB, wr + off[2], B_[2], m2, bufA,
                                                  D1, H1, W1, D2, H2, W2);
    conv_smem_kernel<32, 32, 4, 2, 88, 352, 3, 3, 3, 1, 1, 1, 1, 1, 1>
        <<<dim3(1, H2 / 2, D2), dim3(8, 22, 2)>>>(bufA, wr + off[3], B_[3], m2, bufB,
                                                  D2, H2, W2, D2, H2, W2);
    conv_smem_kernel<32, 32, 4, 2, 88, 352, 3, 3, 3, 1, 1, 1, 1, 1, 1>
        <<<dim3(1, H2 / 2, D2), dim3(8, 22, 2)>>>(bufB, wr + off[4], B_[4], m2, bufA,
                                                  D2, H2, W2, D2, H2, W2);

    mask_pool_kernel<<<(N3 + 255) / 256, 256>>>(m2, m3, D2, H2, W2, D3, H3, W3,
                                                3, 3, 3, 2, 2, 2, 1, 1, 1);
    // stage 3 (OW=44): block (16,11,2)=352
    conv_smem_kernel<32, 64, 4, 2, 44, 352, 3, 3, 3, 2, 2, 2, 1, 1, 1>
        <<<dim3(1, H3 / 2, D3), dim3(16, 11, 2)>>>(bufA, wr + off[5], B_[5], m3, bufB,
                                                   D2, H2, W2, D3, H3, W3);
    conv_smem_kernel<64, 64, 4, 2, 44, 352, 3, 3, 3, 1, 1, 1, 1, 1, 1>
        <<<dim3(1, H3 / 2, D3), dim3(16, 11, 2)>>>(bufB, wr + off[6], B_[6], m3, bufA,
                                                   D3, H3, W3, D3, H3, W3);
    conv_smem_kernel<64, 64, 4, 2, 44, 352, 3, 3, 3, 1, 1, 1, 1, 1, 1>
        <<<dim3(1, H3 / 2, D3), dim3(16, 11, 2)>>>(bufA, wr + off[7], B_[7], m3, bufB,
                                                   D3, H3, W3, D3, H3, W3);

    mask_pool_kernel<<<(N4 + 255) / 256, 256>>>(m3, m4, D3, H3, W3, D4, H4, W4,
                                                3, 3, 3, 2, 2, 2, 0, 1, 1);
    // stage 4 (OW=22): block (16,11,2)=352, V=2
    conv_smem_kernel<64, 64, 2, 2, 22, 352, 3, 3, 3, 2, 2, 2, 0, 1, 1>
        <<<dim3(1, (H4 + 1) / 2, D4), dim3(16, 11, 2)>>>(bufB, wr + off[8], B_[8], m4, bufA,
                                                         D3, H3, W3, D4, H4, W4);
    conv_smem_kernel<64, 64, 2, 2, 22, 352, 3, 3, 3, 1, 1, 1, 1, 1, 1>
        <<<dim3(1, (H4 + 1) / 2, D4), dim3(16, 11, 2)>>>(bufA, wr + off[9], B_[9], m4, bufB,
                                                         D4, H4, W4, D4, H4, W4);
    conv_smem_kernel<64, 64, 2, 2, 22, 352, 3, 3, 3, 1, 1, 1, 1, 1, 1>
        <<<dim3(1, (H4 + 1) / 2, D4), dim3(16, 11, 2)>>>(bufB, wr + off[10], B_[10], m4, bufA,
                                                         D4, H4, W4, D4, H4, W4);

    mask_pool_kernel<<<(N5 + 255) / 256, 256>>>(m4, m5, D4, H4, W4, D5, H5, W5,
                                                3, 1, 1, 2, 1, 1, 0, 0, 0);
    // L11 (OW=22): block (32,11,1)=352, V=2, k(3,1,1) s(2,1,1) p0
    conv_smem_kernel<64, 128, 2, 1, 22, 352, 3, 1, 1, 2, 1, 1, 0, 0, 0>
        <<<dim3(1, H5, D5), dim3(32, 11, 1)>>>(bufA, wr + off[11], B_[11], m5, out,
                                               D4, H4, W4, D5, H5, W5);
}

// round 9
// speedup vs baseline: 1.8045x; 1.2556x over previous
#include <cuda_runtime.h>

typedef unsigned long long ull;

// ---------------- problem dimensions ----------------
static constexpr int D1=41, H1=200, W1=176; static constexpr int N1=D1*H1*W1;   // 1,443,200
static constexpr int D2=21, H2=100, W2=88;  static constexpr int N2=D2*H2*W2;   // 184,800
static constexpr int D3=11, H3=50,  W3=44;  static constexpr int N3=D3*H3*W3;   // 24,200
static constexpr int D4=5,  H4=25,  W4=22;  static constexpr int N4=D4*H4*W4;   // 2,750
static constexpr int D5=2,  H5=25,  W5=22;  static constexpr int N5=D5*H5*W5;   // 1,100

// ---------------- static device scratch ----------------
__device__ __align__(16) float g_bufA[16 * N1];   // 92.4 MB ping
__device__ __align__(16) float g_bufB[16 * N1];   // 92.4 MB pong
__device__ float g_mask2[N2];
__device__ float g_mask3[N3];
__device__ float g_mask4[N4];
__device__ float g_mask5[N5];
__device__ __align__(16) float g_wr[710592];      // reordered weights, all 12 layers
__device__ int   g_list[N1];
__device__ int   g_cnt;

// weight region metadata (floats)
__device__ __constant__ int c_off[12] = {0, 1728, 8640, 22464, 50112, 77760, 133056,
                                         243648, 354240, 464832, 575424, 686016};
__device__ __constant__ int c_CI[12] = {4, 16, 16, 32, 32, 32, 64, 64, 64, 64, 64, 64};
__device__ __constant__ int c_CO[12] = {16, 16, 32, 32, 32, 64, 64, 64, 64, 64, 64, 128};
__device__ __constant__ int c_K3[12] = {27, 27, 27, 27, 27, 27, 27, 27, 27, 27, 27, 3};

struct WPtrs { const float* w[12]; };

// ---------------- f32x2 + cp.async helpers ----------------
__device__ __forceinline__ ull f2_dup(float v) {
    ull r; asm("mov.b64 %0, {%1, %1};" : "=l"(r) : "f"(v)); return r;
}
__device__ __forceinline__ void f2_unpack(ull v, float& lo, float& hi) {
    asm("mov.b64 {%0, %1}, %2;" : "=f"(lo), "=f"(hi) : "l"(v));
}
#define FMA_F32X2(d, a, b, c) \
    asm("fma.rn.f32x2 %0, %1, %2, %3;" : "=l"(d) : "l"(a), "l"(b), "l"(c))

__device__ __forceinline__ void cp4(float* dst, const float* src) {
    unsigned d = (unsigned)__cvta_generic_to_shared(dst);
    asm volatile("cp.async.ca.shared.global [%0], [%1], 4;" :: "r"(d), "l"(src));
}
#define CP_COMMIT() asm volatile("cp.async.commit_group;" ::: "memory")
#define CP_WAIT1()  asm volatile("cp.async.wait_group 1;"  ::: "memory")

// ---------------- prelude kernels ----------------
__global__ void compact_kernel(const float* __restrict__ mask) {
    int i = blockIdx.x * blockDim.x + threadIdx.x;
    if (i < N1 && mask[i] != 0.0f) {
        int p = atomicAdd(&g_cnt, 1);
        g_list[p] = i;
    }
}

__global__ void prep_w_all(WPtrs p, float* __restrict__ wr) {
    int t = blockIdx.x * blockDim.x + threadIdx.x;
    if (t >= 710592) return;
    int L = 0;
    int base = 0;
    #pragma unroll
    for (int i = 0; i < 12; i++) {
        int n = c_CO[i] * c_CI[i] * c_K3[i];
        if (t >= base && t < base + n) { L = i; }
        base += n;
    }
    base = c_off[L];
    int local = t - base;
    int K3 = c_K3[L], CI = c_CI[L], CO = c_CO[L];
    int k  = local % K3;
    int r  = local / K3;
    int ci = r % CI;
    int co = r / CI;
    wr[base + (ci * K3 + k) * CO + co] = p.w[L][local];
}

__global__ void mask_pool_kernel(const float* __restrict__ mi, float* __restrict__ mo,
                                 int ID, int IH, int IW, int OD, int OH, int OW,
                                 int KD, int KH, int KW, int SD, int SH, int SW,
                                 int PD, int PH, int PW) {
    int o = blockIdx.x * blockDim.x + threadIdx.x;
    int n = OD * OH * OW;
    if (o >= n) return;
    int x = o % OW; int t = o / OW; int y = t % OH; int z = t / OH;
    float mx = 0.0f;
    for (int kz = 0; kz < KD; kz++) {
        int zi = z * SD - PD + kz; if ((unsigned)zi >= (unsigned)ID) continue;
        for (int ky = 0; ky < KH; ky++) {
            int yi = y * SH - PH + ky; if ((unsigned)yi >= (unsigned)IH) continue;
            for (int kx = 0; kx < KW; kx++) {
                int xi = x * SW - PW + kx; if ((unsigned)xi >= (unsigned)IW) continue;
                mx = fmaxf(mx, mi[(zi * IH + yi) * IW + xi]);
            }
        }
    }
    mo[o] = (mx > 0.0f) ? 1.0f : 0.0f;
}

// ---------------- sparse gather subm conv (3x3x3, stride1, pad1) ----------------
template<int CI, int CO>
__global__ void subm_gather_kernel(const float* __restrict__ in, const float* __restrict__ wr,
                                   const float* __restrict__ bn, float* __restrict__ out,
                                   int D, int H, int W) {
    const int q = threadIdx.x;       // [0, CO/4)
    const int n = g_cnt;
    for (int e = blockIdx.x * blockDim.y + threadIdx.y; e < n; e += gridDim.x * blockDim.y) {
        const int idx = g_list[e];
        const int x  = idx % W;
        const int zy = idx / W;
        const int y  = zy % H;
        const int z  = zy / H;

        float acc[4] = {0.f, 0.f, 0.f, 0.f};
        for (int ci = 0; ci < CI; ci++) {
            #pragma unroll
            for (int kz = 0; kz < 3; kz++) {
                int zi = z - 1 + kz; if ((unsigned)zi >= (unsigned)D) continue;
                #pragma unroll
                for (int ky = 0; ky < 3; ky++) {
                    int yi = y - 1 + ky; if ((unsigned)yi >= (unsigned)H) continue;
                    const float* __restrict__ prow = in + ((ci * D + zi) * (long)H + yi) * W + x;
                    const float* __restrict__ wrow = wr + ((ci * 3 + kz) * 3 + ky) * 3 * CO + 4 * q;
                    #pragma unroll
                    for (int kx = 0; kx < 3; kx++) {
                        int xi = x - 1 + kx;
                        float iv = ((unsigned)xi < (unsigned)W) ? __ldg(prow + kx - 1) : 0.0f;
                        float4 w4 = *reinterpret_cast<const float4*>(wrow + kx * CO);
                        acc[0] += iv * w4.x;
                        acc[1] += iv * w4.y;
                        acc[2] += iv * w4.z;
                        acc[3] += iv * w4.w;
                    }
                }
            }
        }
        #pragma unroll
        for (int j = 0; j < 4; j++) {
            int co = 4 * q + j;
            float g  = bn[co];
            float b  = bn[CO + co];
            float mu = bn[2 * CO + co];
            float vr = bn[3 * CO + co];
            float sc = g * rsqrtf(vr + 1e-3f);
            float sh = b - mu * sc;
            float val = fmaxf(acc[j] * sc + sh, 0.0f);
            out[((co * D + z) * (long)H + y) * W + x] = val;
        }
    }
}

// ---------------- dense conv: 2-CI cp.async pipeline + hoisted loader + f32x2 ----------------
// block = (CO/4, OWT/V, YB); covers one full x-row, YB y-rows.
// Each pipeline stage loads TWO input channels; loader offsets precomputed once.
template<int CI, int CO, int V, int YB, int OWT, int NT,
         int KD, int KH, int KW, int SD, int SH, int SW, int PD, int PH, int PW>
__global__ void __launch_bounds__(NT, 2)
conv_smem_kernel(const float* __restrict__ in, const float* __restrict__ wr,
                 const float* __restrict__ bn, const float* __restrict__ omask,
                 float* __restrict__ out,
                 int ID, int IH, int IW, int OD, int OH, int OW) {
    constexpr int NSEG  = (V - 1) * SW + KW;
    constexpr int SMH   = (YB - 1) * SH + KH;          // rows per z-plane
    constexpr int SMW   = (OWT - 1) * SW + KW;         // floats per row
    constexpr int SMTOT = KD * SMH * SMW;
    constexpr int NLOAD = (SMTOT + NT - 1) / NT;
    constexpr int NS    = CI / 2;                      // pipeline stages (2 CI each)

    __shared__ float sm[2][2 * SMTOT];

    const int q   = threadIdx.x;                        // channel quad
    const int tz  = threadIdx.z;
    const int x0  = threadIdx.y * V;
    const int y   = blockIdx.y * YB + tz;
    const int z   = blockIdx.z;
    const int tid = threadIdx.x + blockDim.x * (threadIdx.y + blockDim.y * threadIdx.z);

    const bool active = (y < OH);
    const int CIstride = ID * IH * IW;

    // zero both buffers once (OOB cells stay zero forever)
    for (int i = tid; i < 4 * SMTOT; i += NT)
        (&sm[0][0])[i] = 0.0f;

    // ---- precompute loader tuples (CI-invariant geometry) ----
    const int zi_base = z * SD - PD;
    const int yi_base = blockIdx.y * YB * SH - PH;
    int goff[NLOAD];
    unsigned vm = 0;
    #pragma unroll
    for (int j = 0; j < NLOAD; j++) {
        int i  = tid + j * NT;
        int s  = i % SMW;
        int t2 = i / SMW;
        int r  = t2 % SMH;
        int kz = t2 / SMH;
        int zi = zi_base + kz;
        int yi = yi_base + r;
        int xi = s - PW;
        bool ok = (i < SMTOT) && ((unsigned)zi < (unsigned)ID) &&
                  ((unsigned)yi < (unsigned)IH) && ((unsigned)xi < (unsigned)IW);
        goff[j] = ok ? ((zi * IH + yi) * IW + xi) : 0;
        if (ok) vm |= (1u << j);
    }
    __syncthreads();

    // masks
    float m[V];
    float msum = 0.0f;
    if (active) {
        const int obase = (z * OH + y) * OW;
        #pragma unroll
        for (int v = 0; v < V; v++) {
            m[v] = (x0 + v < OW) ? omask[obase + x0 + v] : 0.0f;
            msum += m[v];
        }
    } else {
        #pragma unroll
        for (int v = 0; v < V; v++) m[v] = 0.0f;
    }
    const bool any = active && (msum > 0.0f);

    ull acc[V][2];
    #pragma unroll
    for (int v = 0; v < V; v++) { acc[v][0] = 0ull; acc[v][1] = 0ull; }

    // loader: fetch CI pair (ci0, ci0+1) into buffer b
    auto load2 = [&](int ci0, int b) {
        const float* __restrict__ base0 = in + (long)ci0 * CIstride;
        #pragma unroll
        for (int j = 0; j < NLOAD; j++)
            if (vm & (1u << j)) cp4(&sm[b][tid + j * NT], base0 + goff[j]);
        #pragma unroll
        for (int j = 0; j < NLOAD; j++)
            if (vm & (1u << j)) cp4(&sm[b][SMTOT + tid + j * NT], base0 + CIstride + goff[j]);
    };

    load2(0, 0);
    CP_COMMIT();

    for (int st = 0; st < NS; st++) {
        if (st + 1 < NS) load2(2 * (st + 1), (st + 1) & 1);
        CP_COMMIT();
        CP_WAIT1();
        __syncthreads();

        if (any) {
            #pragma unroll
            for (int cc = 0; cc < 2; cc++) {
                const float* __restrict__ smb = &sm[st & 1][cc * SMTOT];
                const float* __restrict__ wci =
                    wr + (2 * st + cc) * (KD * KH * KW * CO) + 4 * q;
                #pragma unroll
                for (int kz = 0; kz < KD; kz++) {
                    #pragma unroll
                    for (int ky = 0; ky < KH; ky++) {
                        const float* __restrict__ row =
                            smb + ((kz * SMH) + tz * SH + ky) * SMW + x0 * SW;
                        ull iv2[NSEG];
                        #pragma unroll
                        for (int s = 0; s < NSEG; s++)
                            iv2[s] = f2_dup(row[s]);
                        const float* __restrict__ wrow = wci + (kz * KH + ky) * KW * CO;
                        #pragma unroll
                        for (int kx = 0; kx < KW; kx++) {
                            union { float4 f; ull u[2]; } wu;
                            wu.f = *reinterpret_cast<const float4*>(wrow + kx * CO);
                            #pragma unroll
                            for (int v = 0; v < V; v++) {
                                ull iv = iv2[v * SW + kx];
                                FMA_F32X2(acc[v][0], iv, wu.u[0], acc[v][0]);
                                FMA_F32X2(acc[v][1], iv, wu.u[1], acc[v][1]);
                            }
                        }
                    }
                }
            }
        }
        __syncthreads();
    }

    if (active) {
        #pragma unroll
        for (int j = 0; j < 2; j++) {
            int ca = 4 * q + 2 * j, cb = ca + 1;
            float sca = bn[ca] * rsqrtf(bn[3 * CO + ca] + 1e-3f);
            float sha = bn[CO + ca] - bn[2 * CO + ca] * sca;
            float scb = bn[cb] * rsqrtf(bn[3 * CO + cb] + 1e-3f);
            float shb = bn[CO + cb] - bn[2 * CO + cb] * scb;
            #pragma unroll
            for (int v = 0; v < V; v++) {
                int x = x0 + v;
                if (x < OW) {
                    float a0, a1; f2_unpack(acc[v][j], a0, a1);
                    bool act = m[v] > 0.0f;
                    out[((ca * OD + z) * (long)OH + y) * OW + x] =
                        act ? fmaxf(fmaf(a0, sca, sha), 0.0f) : 0.0f;
                    out[((cb * OD + z) * (long)OH + y) * OW + x] =
                        act ? fmaxf(fmaf(a1, scb, shb), 0.0f) : 0.0f;
                }
            }
        }
    }
}

// ---------------- launch ----------------
extern "C" void kernel_launch(void* const* d_in, const int* in_sizes, int n_in,
                              void* d_out, int out_size) {
    const float* x    = (const float*)d_in[0];
    const float* mask = (const float*)d_in[1];
    WPtrs wp;
    const float* B_[12];
    for (int i = 0; i < 12; i++) {
        wp.w[i] = (const float*)d_in[2 + 2 * i];
        B_[i]   = (const float*)d_in[3 + 2 * i];
    }
    float* out = (float*)d_out;

    float *bufA, *bufB, *wr, *m2, *m3, *m4, *m5;
    int* cntp;
    cudaGetSymbolAddress((void**)&bufA, g_bufA);
    cudaGetSymbolAddress((void**)&bufB, g_bufB);
    cudaGetSymbolAddress((void**)&wr,   g_wr);
    cudaGetSymbolAddress((void**)&m2,   g_mask2);
    cudaGetSymbolAddress((void**)&m3,   g_mask3);
    cudaGetSymbolAddress((void**)&m4,   g_mask4);
    cudaGetSymbolAddress((void**)&m5,   g_mask5);
    cudaGetSymbolAddress((void**)&cntp, g_cnt);

    static const int off[12] = {0, 1728, 8640, 22464, 50112, 77760, 133056,
                                243648, 354240, 464832, 575424, 686016};

    cudaMemsetAsync(cntp, 0, sizeof(int), 0);
    cudaMemsetAsync(bufA, 0, sizeof(float) * 16 * (size_t)N1, 0);
    cudaMemsetAsync(bufB, 0, sizeof(float) * 16 * (size_t)N1, 0);

    prep_w_all<<<(710592 + 255) / 256, 256>>>(wp, wr);
    compact_kernel<<<(N1 + 255) / 256, 256>>>(mask);

    subm_gather_kernel<4, 16><<<1024, dim3(4, 32)>>>(x, wr + off[0], B_[0], bufA, D1, H1, W1);
    subm_gather_kernel<16, 16><<<1024, dim3(4, 32)>>>(bufA, wr + off[1], B_[1], bufB, D1, H1, W1);

    // launch 4: mask2 ; launch 5: L2 dense conv
    mask_pool_kernel<<<(N2 + 255) / 256, 256>>>(mask, m2, D1, H1, W1, D2, H2, W2,
                                                3, 3, 3, 2, 2, 2, 1, 1, 1);
    // stage 2 (OW=88): block (8,22,2)=352
    conv_smem_kernel<16, 32, 4, 2, 88, 352, 3, 3, 3, 2, 2, 2, 1, 1, 1>
        <<<dim3(1, H2 / 2, D2), dim3(8, 22, 2)>>>(bufB, wr + off[2], B_[2], m2, bufA,
                                                  D1, H1, W1, D2, H2, W2);
    conv_smem_kernel<32, 32, 4, 2, 88, 352, 3, 3, 3, 1, 1, 1, 1, 1, 1>
        <<<dim3(1, H2 / 2, D2), dim3(8, 22, 2)>>>(bufA, wr + off[3], B_[3], m2, bufB,
                                                  D2, H2, W2, D2, H2, W2);
    conv_smem_kernel<32, 32, 4, 2, 88, 352, 3, 3, 3, 1, 1, 1, 1, 1, 1>
        <<<dim3(1, H2 / 2, D2), dim3(8, 22, 2)>>>(bufB, wr + off[4], B_[4], m2, bufA,
                                                  D2, H2, W2, D2, H2, W2);

    mask_pool_kernel<<<(N3 + 255) / 256, 256>>>(m2, m3, D2, H2, W2, D3, H3, W3,
                                                3, 3, 3, 2, 2, 2, 1, 1, 1);
    // stage 3 (OW=44): block (16,11,2)=352
    conv_smem_kernel<32, 64, 4, 2, 44, 352, 3, 3, 3, 2, 2, 2, 1, 1, 1>
        <<<dim3(1, H3 / 2, D3), dim3(16, 11, 2)>>>(bufA, wr + off[5], B_[5], m3, bufB,
                                                   D2, H2, W2, D3, H3, W3);
    conv_smem_kernel<64, 64, 4, 2, 44, 352, 3, 3, 3, 1, 1, 1, 1, 1, 1>
        <<<dim3(1, H3 / 2, D3), dim3(16, 11, 2)>>>(bufB, wr + off[6], B_[6], m3, bufA,
                                                   D3, H3, W3, D3, H3, W3);
    conv_smem_kernel<64, 64, 4, 2, 44, 352, 3, 3, 3, 1, 1, 1, 1, 1, 1>
        <<<dim3(1, H3 / 2, D3), dim3(16, 11, 2)>>>(bufA, wr + off[7], B_[7], m3, bufB,
                                                   D3, H3, W3, D3, H3, W3);

    mask_pool_kernel<<<(N4 + 255) / 256, 256>>>(m3, m4, D3, H3, W3, D4, H4, W4,
                                                3, 3, 3, 2, 2, 2, 0, 1, 1);
    // stage 4 (OW=22): YB=1, block (16,11,1)=176 -> 125 blocks
    conv_smem_kernel<64, 64, 2, 1, 22, 176, 3, 3, 3, 2, 2, 2, 0, 1, 1>
        <<<dim3(1, H4, D4), dim3(16, 11, 1)>>>(bufB, wr + off[8], B_[8], m4, bufA,
                                               D3, H3, W3, D4, H4, W4);
    conv_smem_kernel<64, 64, 2, 1, 22, 176, 3, 3, 3, 1, 1, 1, 1, 1, 1>
        <<<dim3(1, H4, D4), dim3(16, 11, 1)>>>(bufA, wr + off[9], B_[9], m4, bufB,
                                               D4, H4, W4, D4, H4, W4);
    conv_smem_kernel<64, 64, 2, 1, 22, 176, 3, 3, 3, 1, 1, 1, 1, 1, 1>
        <<<dim3(1, H4, D4), dim3(16, 11, 1)>>>(bufB, wr + off[10], B_[10], m4, bufA,
                                               D4, H4, W4, D4, H4, W4);

    mask_pool_kernel<<<(N5 + 255) / 256, 256>>>(m4, m5, D4, H4, W4, D5, H5, W5,
                                                3, 1, 1, 2, 1, 1, 0, 0, 0);
    // L11 (OW=22): block (32,11,1)=352, k(3,1,1) s(2,1,1) p0
    conv_smem_kernel<64, 128, 2, 1, 22, 352, 3, 1, 1, 2, 1, 1, 0, 0, 0>
        <<<dim3(1, H5, D5), dim3(32, 11, 1)>>>(bufA, wr + off[11], B_[11], m5, out,
                                               D4, H4, W4, D5, H5, W5);
}

// round 10
// speedup vs baseline: 1.9082x; 1.0575x over previous
#include <cuda_runtime.h>

typedef unsigned long long ull;

// ---------------- problem dimensions ----------------
static constexpr int D1=41, H1=200, W1=176; static constexpr int N1=D1*H1*W1;   // 1,443,200
static constexpr int D2=21, H2=100, W2=88;  static constexpr int N2=D2*H2*W2;   // 184,800
static constexpr int D3=11, H3=50,  W3=44;  static constexpr int N3=D3*H3*W3;   // 24,200
static constexpr int D4=5,  H4=25,  W4=22;  static constexpr int N4=D4*H4*W4;   // 2,750
static constexpr int D5=2,  H5=25,  W5=22;  static constexpr int N5=D5*H5*W5;   // 1,100

// ---------------- static device scratch ----------------
__device__ __align__(16) float g_bufA[16 * N1];   // 92.4 MB ping
__device__ __align__(16) float g_bufB[16 * N1];   // 92.4 MB pong
__device__ float g_mask2[N2];
__device__ float g_mask3[N3];
__device__ float g_mask4[N4];
__device__ float g_mask5[N5];
__device__ __align__(16) float g_wr[710592];      // reordered weights, all 12 layers
__device__ int   g_list[N1];
__device__ int   g_cnt;

// weight region metadata (floats)
__device__ __constant__ int c_off[12] = {0, 1728, 8640, 22464, 50112, 77760, 133056,
                                         243648, 354240, 464832, 575424, 686016};
__device__ __constant__ int c_CI[12] = {4, 16, 16, 32, 32, 32, 64, 64, 64, 64, 64, 64};
__device__ __constant__ int c_CO[12] = {16, 16, 32, 32, 32, 64, 64, 64, 64, 64, 64, 128};
__device__ __constant__ int c_K3[12] = {27, 27, 27, 27, 27, 27, 27, 27, 27, 27, 27, 3};

struct WPtrs { const float* w[12]; };

// ---------------- f32x2 + cp.async helpers ----------------
__device__ __forceinline__ ull f2_dup(float v) {
    ull r; asm("mov.b64 %0, {%1, %1};" : "=l"(r) : "f"(v)); return r;
}
__device__ __forceinline__ void f2_unpack(ull v, float& lo, float& hi) {
    asm("mov.b64 {%0, %1}, %2;" : "=f"(lo), "=f"(hi) : "l"(v));
}
#define FMA_F32X2(d, a, b, c) \
    asm("fma.rn.f32x2 %0, %1, %2, %3;" : "=l"(d) : "l"(a), "l"(b), "l"(c))

__device__ __forceinline__ void cp4(float* dst, const float* src) {
    unsigned d = (unsigned)__cvta_generic_to_shared(dst);
    asm volatile("cp.async.ca.shared.global [%0], [%1], 4;" :: "r"(d), "l"(src));
}
#define CP_COMMIT() asm volatile("cp.async.commit_group;" ::: "memory")
#define CP_WAIT1()  asm volatile("cp.async.wait_group 1;"  ::: "memory")

// ---------------- prelude kernels ----------------
// weight reorder for all 12 layers + zero bufB (the only buffer needing zeros)
__global__ void prep_w_all(WPtrs p, float* __restrict__ wr, float4* __restrict__ zb) {
    int t = blockIdx.x * blockDim.x + threadIdx.x;
    int nt = gridDim.x * blockDim.x;
    // zero bufB (16*N1 floats = 5,772,800 float4)
    const int NZ4 = (16 * N1) / 4;
    for (int i = t; i < NZ4; i += nt)
        zb[i] = make_float4(0.f, 0.f, 0.f, 0.f);
    if (t >= 710592) return;
    int L = 0;
    int base = 0;
    #pragma unroll
    for (int i = 0; i < 12; i++) {
        int n = c_CO[i] * c_CI[i] * c_K3[i];
        if (t >= base && t < base + n) { L = i; }
        base += n;
    }
    base = c_off[L];
    int local = t - base;
    int K3 = c_K3[L], CI = c_CI[L], CO = c_CO[L];
    int k  = local % K3;
    int r  = local / K3;
    int ci = r % CI;
    int co = r / CI;
    wr[base + (ci * K3 + k) * CO + co] = p.w[L][local];
}

// compact active list AND compute mask2 (dilate 3^3 stride2 pad1) in one kernel
__global__ void compact_mask2_kernel(const float* __restrict__ mask, float* __restrict__ mo) {
    int i = blockIdx.x * blockDim.x + threadIdx.x;
    if (i < N1 && mask[i] != 0.0f) {
        int p = atomicAdd(&g_cnt, 1);
        g_list[p] = i;
    }
    if (i < N2) {
        int x = i % W2; int t = i / W2; int y = t % H2; int z = t / H2;
        float mx = 0.0f;
        #pragma unroll
        for (int kz = 0; kz < 3; kz++) {
            int zi = z * 2 - 1 + kz; if ((unsigned)zi >= (unsigned)D1) continue;
            #pragma unroll
            for (int ky = 0; ky < 3; ky++) {
                int yi = y * 2 - 1 + ky; if ((unsigned)yi >= (unsigned)H1) continue;
                #pragma unroll
                for (int kx = 0; kx < 3; kx++) {
                    int xi = x * 2 - 1 + kx; if ((unsigned)xi >= (unsigned)W1) continue;
                    mx = fmaxf(mx, mask[(zi * H1 + yi) * W1 + xi]);
                }
            }
        }
        mo[i] = (mx > 0.0f) ? 1.0f : 0.0f;
    }
}

__global__ void mask_pool_kernel(const float* __restrict__ mi, float* __restrict__ mo,
                                 int ID, int IH, int IW, int OD, int OH, int OW,
                                 int KD, int KH, int KW, int SD, int SH, int SW,
                                 int PD, int PH, int PW) {
    int o = blockIdx.x * blockDim.x + threadIdx.x;
    int n = OD * OH * OW;
    if (o >= n) return;
    int x = o % OW; int t = o / OW; int y = t % OH; int z = t / OH;
    float mx = 0.0f;
    for (int kz = 0; kz < KD; kz++) {
        int zi = z * SD - PD + kz; if ((unsigned)zi >= (unsigned)ID) continue;
        for (int ky = 0; ky < KH; ky++) {
            int yi = y * SH - PH + ky; if ((unsigned)yi >= (unsigned)IH) continue;
            for (int kx = 0; kx < KW; kx++) {
                int xi = x * SW - PW + kx; if ((unsigned)xi >= (unsigned)IW) continue;
                mx = fmaxf(mx, mi[(zi * IH + yi) * IW + xi]);
            }
        }
    }
    mo[o] = (mx > 0.0f) ? 1.0f : 0.0f;
}

// ---------------- sparse gather subm conv with TAP SKIP (3x3x3, s1, p1) ----------------
// A tap contributes only if mask[tap site]!=0 (input is exactly 0 elsewhere).
// At 2% density this skips ~95% of the CI-loop work.
template<int CI, int CO>
__global__ void subm_gather_kernel(const float* __restrict__ in, const float* __restrict__ mask,
                                   const float* __restrict__ wr, const float* __restrict__ bn,
                                   float* __restrict__ out, int D, int H, int W) {
    const int q = threadIdx.x;       // [0, CO/4)
    const int n = g_cnt;
    const int DHW = D * H * W;
    for (int e = blockIdx.x * blockDim.y + threadIdx.y; e < n; e += gridDim.x * blockDim.y) {
        const int idx = g_list[e];
        const int x  = idx % W;
        const int zy = idx / W;
        const int y  = zy % H;
        const int z  = zy / H;

        float acc[4] = {0.f, 0.f, 0.f, 0.f};
        #pragma unroll
        for (int kz = 0; kz < 3; kz++) {
            int zi = z - 1 + kz; if ((unsigned)zi >= (unsigned)D) continue;
            #pragma unroll
            for (int ky = 0; ky < 3; ky++) {
                int yi = y - 1 + ky; if ((unsigned)yi >= (unsigned)H) continue;
                const int rowb = (zi * H + yi) * W + x;
                #pragma unroll
                for (int kx = 0; kx < 3; kx++) {
                    int xi = x - 1 + kx;
                    if ((unsigned)xi >= (unsigned)W) continue;
                    if (__ldg(mask + rowb + kx - 1) == 0.0f) continue;   // tap skip
                    const float* __restrict__ ptap = in + rowb + kx - 1;
                    const float* __restrict__ wtap =
                        wr + ((kz * 3 + ky) * 3 + kx) * CO + 4 * q;
                    #pragma unroll
                    for (int ci = 0; ci < CI; ci++) {
                        float iv = __ldg(ptap + ci * DHW);
                        float4 w4 = *reinterpret_cast<const float4*>(wtap + ci * 27 * CO);
                        acc[0] += iv * w4.x;
                        acc[1] += iv * w4.y;
                        acc[2] += iv * w4.z;
                        acc[3] += iv * w4.w;
                    }
                }
            }
        }
        #pragma unroll
        for (int j = 0; j < 4; j++) {
            int co = 4 * q + j;
            float g  = bn[co];
            float b  = bn[CO + co];
            float mu = bn[2 * CO + co];
            float vr = bn[3 * CO + co];
            float sc = g * rsqrtf(vr + 1e-3f);
            float sh = b - mu * sc;
            float val = fmaxf(acc[j] * sc + sh, 0.0f);
            out[((co * D + z) * (long)H + y) * W + x] = val;
        }
    }
}

// ---------------- dense conv: 2-CI cp.async pipeline + hoisted loader + f32x2 ----------------
// (unchanged from R8 — protected win)
template<int CI, int CO, int V, int YB, int OWT, int NT,
         int KD, int KH, int KW, int SD, int SH, int SW, int PD, int PH, int PW>
__global__ void __launch_bounds__(NT, 2)
conv_smem_kernel(const float* __restrict__ in, const float* __restrict__ wr,
                 const float* __restrict__ bn, const float* __restrict__ omask,
                 float* __restrict__ out,
                 int ID, int IH, int IW, int OD, int OH, int OW) {
    constexpr int NSEG  = (V - 1) * SW + KW;
    constexpr int SMH   = (YB - 1) * SH + KH;
    constexpr int SMW   = (OWT - 1) * SW + KW;
    constexpr int SMTOT = KD * SMH * SMW;
    constexpr int NLOAD = (SMTOT + NT - 1) / NT;
    constexpr int NS    = CI / 2;

    __shared__ float sm[2][2 * SMTOT];

    const int q   = threadIdx.x;
    const int tz  = threadIdx.z;
    const int x0  = threadIdx.y * V;
    const int y   = blockIdx.y * YB + tz;
    const int z   = blockIdx.z;
    const int tid = threadIdx.x + blockDim.x * (threadIdx.y + blockDim.y * threadIdx.z);

    const bool active = (y < OH);
    const int CIstride = ID * IH * IW;

    for (int i = tid; i < 4 * SMTOT; i += NT)
        (&sm[0][0])[i] = 0.0f;

    const int zi_base = z * SD - PD;
    const int yi_base = blockIdx.y * YB * SH - PH;
    int goff[NLOAD];
    unsigned vm = 0;
    #pragma unroll
    for (int j = 0; j < NLOAD; j++) {
        int i  = tid + j * NT;
        int s  = i % SMW;
        int t2 = i / SMW;
        int r  = t2 % SMH;
        int kz = t2 / SMH;
        int zi = zi_base + kz;
        int yi = yi_base + r;
        int xi = s - PW;
        bool ok = (i < SMTOT) && ((unsigned)zi < (unsigned)ID) &&
                  ((unsigned)yi < (unsigned)IH) && ((unsigned)xi < (unsigned)IW);
        goff[j] = ok ? ((zi * IH + yi) * IW + xi) : 0;
        if (ok) vm |= (1u << j);
    }
    __syncthreads();

    float m[V];
    float msum = 0.0f;
    if (active) {
        const int obase = (z * OH + y) * OW;
        #pragma unroll
        for (int v = 0; v < V; v++) {
            m[v] = (x0 + v < OW) ? omask[obase + x0 + v] : 0.0f;
            msum += m[v];
        }
    } else {
        #pragma unroll
        for (int v = 0; v < V; v++) m[v] = 0.0f;
    }
    const bool any = active && (msum > 0.0f);

    ull acc[V][2];
    #pragma unroll
    for (int v = 0; v < V; v++) { acc[v][0] = 0ull; acc[v][1] = 0ull; }

    auto load2 = [&](int ci0, int b) {
        const float* __restrict__ base0 = in + (long)ci0 * CIstride;
        #pragma unroll
        for (int j = 0; j < NLOAD; j++)
            if (vm & (1u << j)) cp4(&sm[b][tid + j * NT], base0 + goff[j]);
        #pragma unroll
        for (int j = 0; j < NLOAD; j++)
            if (vm & (1u << j)) cp4(&sm[b][SMTOT + tid + j * NT], base0 + CIstride + goff[j]);
    };

    load2(0, 0);
    CP_COMMIT();

    for (int st = 0; st < NS; st++) {
        if (st + 1 < NS) load2(2 * (st + 1), (st + 1) & 1);
        CP_COMMIT();
        CP_WAIT1();
        __syncthreads();

        if (any) {
            #pragma unroll
            for (int cc = 0; cc < 2; cc++) {
                const float* __restrict__ smb = &sm[st & 1][cc * SMTOT];
                const float* __restrict__ wci =
                    wr + (2 * st + cc) * (KD * KH * KW * CO) + 4 * q;
                #pragma unroll
                for (int kz = 0; kz < KD; kz++) {
                    #pragma unroll
                    for (int ky = 0; ky < KH; ky++) {
                        const float* __restrict__ row =
                            smb + ((kz * SMH) + tz * SH + ky) * SMW + x0 * SW;
                        ull iv2[NSEG];
                        #pragma unroll
                        for (int s = 0; s < NSEG; s++)
                            iv2[s] = f2_dup(row[s]);
                        const float* __restrict__ wrow = wci + (kz * KH + ky) * KW * CO;
                        #pragma unroll
                        for (int kx = 0; kx < KW; kx++) {
                            union { float4 f; ull u[2]; } wu;
                            wu.f = *reinterpret_cast<const float4*>(wrow + kx * CO);
                            #pragma unroll
                            for (int v = 0; v < V; v++) {
                                ull iv = iv2[v * SW + kx];
                                FMA_F32X2(acc[v][0], iv, wu.u[0], acc[v][0]);
                                FMA_F32X2(acc[v][1], iv, wu.u[1], acc[v][1]);
                            }
                        }
                    }
                }
            }
        }
        __syncthreads();
    }

    if (active) {
        #pragma unroll
        for (int j = 0; j < 2; j++) {
            int ca = 4 * q + 2 * j, cb = ca + 1;
            float sca = bn[ca] * rsqrtf(bn[3 * CO + ca] + 1e-3f);
            float sha = bn[CO + ca] - bn[2 * CO + ca] * sca;
            float scb = bn[cb] * rsqrtf(bn[3 * CO + cb] + 1e-3f);
            float shb = bn[CO + cb] - bn[2 * CO + cb] * scb;
            #pragma unroll
            for (int v = 0; v < V; v++) {
                int x = x0 + v;
                if (x < OW) {
                    float a0, a1; f2_unpack(acc[v][j], a0, a1);
                    bool act = m[v] > 0.0f;
                    out[((ca * OD + z) * (long)OH + y) * OW + x] =
                        act ? fmaxf(fmaf(a0, sca, sha), 0.0f) : 0.0f;
                    out[((cb * OD + z) * (long)OH + y) * OW + x] =
                        act ? fmaxf(fmaf(a1, scb, shb), 0.0f) : 0.0f;
                }
            }
        }
    }
}

// ---------------- launch ----------------
extern "C" void kernel_launch(void* const* d_in, const int* in_sizes, int n_in,
                              void* d_out, int out_size) {
    const float* x    = (const float*)d_in[0];
    const float* mask = (const float*)d_in[1];
    WPtrs wp;
    const float* B_[12];
    for (int i = 0; i < 12; i++) {
        wp.w[i] = (const float*)d_in[2 + 2 * i];
        B_[i]   = (const float*)d_in[3 + 2 * i];
    }
    float* out = (float*)d_out;

    float *bufA, *bufB, *wr, *m2, *m3, *m4, *m5;
    int* cntp;
    cudaGetSymbolAddress((void**)&bufA, g_bufA);
    cudaGetSymbolAddress((void**)&bufB, g_bufB);
    cudaGetSymbolAddress((void**)&wr,   g_wr);
    cudaGetSymbolAddress((void**)&m2,   g_mask2);
    cudaGetSymbolAddress((void**)&m3,   g_mask3);
    cudaGetSymbolAddress((void**)&m4,   g_mask4);
    cudaGetSymbolAddress((void**)&m5,   g_mask5);
    cudaGetSymbolAddress((void**)&cntp, g_cnt);

    static const int off[12] = {0, 1728, 8640, 22464, 50112, 77760, 133056,
                                243648, 354240, 464832, 575424, 686016};

    cudaMemsetAsync(cntp, 0, sizeof(int), 0);   // 4B DMA fill (not a kernel launch)

    // launch 0: weights reorder + zero bufB ; launch 1: compact + mask2
    prep_w_all<<<2776, 256>>>(wp, wr, (float4*)bufB);
    compact_mask2_kernel<<<(N1 + 255) / 256, 256>>>(mask, m2);

    // launch 2,3: gather subm with tap skip (bufA needs NO zeroing now)
    subm_gather_kernel<4, 16><<<1024, dim3(4, 32)>>>(x, mask, wr + off[0], B_[0], bufA, D1, H1, W1);
    subm_gather_kernel<16, 16><<<1024, dim3(4, 32)>>>(bufA, mask, wr + off[1], B_[1], bufB, D1, H1, W1);

    // launch 4: L2 ; launch 5: L3  <-- ncu -s 5 lands on L3 (biggest layer)
    conv_smem_kernel<16, 32, 4, 2, 88, 352, 3, 3, 3, 2, 2, 2, 1, 1, 1>
        <<<dim3(1, H2 / 2, D2), dim3(8, 22, 2)>>>(bufB, wr + off[2], B_[2], m2, bufA,
                                                  D1, H1, W1, D2, H2, W2);
    conv_smem_kernel<32, 32, 4, 2, 88, 352, 3, 3, 3, 1, 1, 1, 1, 1, 1>
        <<<dim3(1, H2 / 2, D2), dim3(8, 22, 2)>>>(bufA, wr + off[3], B_[3], m2, bufB,
                                                  D2, H2, W2, D2, H2, W2);
    conv_smem_kernel<32, 32, 4, 2, 88, 352, 3, 3, 3, 1, 1, 1, 1, 1, 1>
        <<<dim3(1, H2 / 2, D2), dim3(8, 22, 2)>>>(bufB, wr + off[4], B_[4], m2, bufA,
                                                  D2, H2, W2, D2, H2, W2);

    mask_pool_kernel<<<(N3 + 255) / 256, 256>>>(m2, m3, D2, H2, W2, D3, H3, W3,
                                                3, 3, 3, 2, 2, 2, 1, 1, 1);
    conv_smem_kernel<32, 64, 4, 2, 44, 352, 3, 3, 3, 2, 2, 2, 1, 1, 1>
        <<<dim3(1, H3 / 2, D3), dim3(16, 11, 2)>>>(bufA, wr + off[5], B_[5], m3, bufB,
                                                   D2, H2, W2, D3, H3, W3);
    conv_smem_kernel<64, 64, 4, 2, 44, 352, 3, 3, 3, 1, 1, 1, 1, 1, 1>
        <<<dim3(1, H3 / 2, D3), dim3(16, 11, 2)>>>(bufB, wr + off[6], B_[6], m3, bufA,
                                                   D3, H3, W3, D3, H3, W3);
    conv_smem_kernel<64, 64, 4, 2, 44, 352, 3, 3, 3, 1, 1, 1, 1, 1, 1>
        <<<dim3(1, H3 / 2, D3), dim3(16, 11, 2)>>>(bufA, wr + off[7], B_[7], m3, bufB,
                                                   D3, H3, W3, D3, H3, W3);

    mask_pool_kernel<<<(N4 + 255) / 256, 256>>>(m3, m4, D3, H3, W3, D4, H4, W4,
                                                3, 3, 3, 2, 2, 2, 0, 1, 1);
    conv_smem_kernel<64, 64, 2, 1, 22, 176, 3, 3, 3, 2, 2, 2, 0, 1, 1>
        <<<dim3(1, H4, D4), dim3(16, 11, 1)>>>(bufB, wr + off[8], B_[8], m4, bufA,
                                               D3, H3, W3, D4, H4, W4);
    conv_smem_kernel<64, 64, 2, 1, 22, 176, 3, 3, 3, 1, 1, 1, 1, 1, 1>
        <<<dim3(1, H4, D4), dim3(16, 11, 1)>>>(bufA, wr + off[9], B_[9], m4, bufB,
                                               D4, H4, W4, D4, H4, W4);
    conv_smem_kernel<64, 64, 2, 1, 22, 176, 3, 3, 3, 1, 1, 1, 1, 1, 1>
        <<<dim3(1, H4, D4), dim3(16, 11, 1)>>>(bufB, wr + off[10], B_[10], m4, bufA,
                                               D4, H4, W4, D4, H4, W4);

    mask_pool_kernel<<<(N5 + 255) / 256, 256>>>(m4, m5, D4, H4, W4, D5, H5, W5,
                                                3, 1, 1, 2, 1, 1, 0, 0, 0);
    conv_smem_kernel<64, 128, 2, 1, 22, 352, 3, 1, 1, 2, 1, 1, 0, 0, 0>
        <<<dim3(1, H5, D5), dim3(32, 11, 1)>>>(bufA, wr + off[11], B_[11], m5, out,
                                               D4, H4, W4, D5, H5, W5);
}

// round 11
// speedup vs baseline: 1.9821x; 1.0387x over previous
#include <cuda_runtime.h>

typedef unsigned long long ull;

// ---------------- problem dimensions ----------------
static constexpr int D1=41, H1=200, W1=176; static constexpr int N1=D1*H1*W1;   // 1,443,200
static constexpr int D2=21, H2=100, W2=88;  static constexpr int N2=D2*H2*W2;   // 184,800
static constexpr int D3=11, H3=50,  W3=44;  static constexpr int N3=D3*H3*W3;   // 24,200
static constexpr int D4=5,  H4=25,  W4=22;  static constexpr int N4=D4*H4*W4;   // 2,750
static constexpr int D5=2,  H5=25,  W5=22;  static constexpr int N5=D5*H5*W5;   // 1,100

// ---------------- static device scratch ----------------
__device__ __align__(16) float g_bufA[16 * N1];   // 92.4 MB ping
__device__ __align__(16) float g_bufB[16 * N1];   // 92.4 MB pong
__device__ float g_mask2[N2];
__device__ float g_mask3[N3];
__device__ float g_mask4[N4];
__device__ float g_mask5[N5];
__device__ __align__(16) float g_wr[710592];      // reordered weights, all 12 layers
__device__ int   g_list[N1];
__device__ int   g_cnt;

// weight region metadata (floats)
__device__ __constant__ int c_off[12] = {0, 1728, 8640, 22464, 50112, 77760, 133056,
                                         243648, 354240, 464832, 575424, 686016};
__device__ __constant__ int c_CI[12] = {4, 16, 16, 32, 32, 32, 64, 64, 64, 64, 64, 64};
__device__ __constant__ int c_CO[12] = {16, 16, 32, 32, 32, 64, 64, 64, 64, 64, 64, 128};
__device__ __constant__ int c_K3[12] = {27, 27, 27, 27, 27, 27, 27, 27, 27, 27, 27, 3};

struct WPtrs { const float* w[12]; };

// ---------------- f32x2 + cp.async helpers ----------------
__device__ __forceinline__ ull f2_dup(float v) {
    ull r; asm("mov.b64 %0, {%1, %1};" : "=l"(r) : "f"(v)); return r;
}
__device__ __forceinline__ void f2_unpack(ull v, float& lo, float& hi) {
    asm("mov.b64 {%0, %1}, %2;" : "=f"(lo), "=f"(hi) : "l"(v));
}
#define FMA_F32X2(d, a, b, c) \
    asm("fma.rn.f32x2 %0, %1, %2, %3;" : "=l"(d) : "l"(a), "l"(b), "l"(c))

__device__ __forceinline__ void cp4(float* dst, const float* src) {
    unsigned d = (unsigned)__cvta_generic_to_shared(dst);
    asm volatile("cp.async.ca.shared.global [%0], [%1], 4;" :: "r"(d), "l"(src));
}
#define CP_COMMIT() asm volatile("cp.async.commit_group;" ::: "memory")
#define CP_WAIT1()  asm volatile("cp.async.wait_group 1;"  ::: "memory")

// ---------------- prelude kernels ----------------
// weight reorder for all 12 layers + zero bufB + zero g_cnt (no memset launches)
__global__ void prep_w_all(WPtrs p, float* __restrict__ wr, float4* __restrict__ zb) {
    int t = blockIdx.x * blockDim.x + threadIdx.x;
    int nt = gridDim.x * blockDim.x;
    if (t == 0) g_cnt = 0;
    const int NZ4 = (16 * N1) / 4;
    for (int i = t; i < NZ4; i += nt)
        zb[i] = make_float4(0.f, 0.f, 0.f, 0.f);
    if (t >= 710592) return;
    int L = 0;
    int base = 0;
    #pragma unroll
    for (int i = 0; i < 12; i++) {
        int n = c_CO[i] * c_CI[i] * c_K3[i];
        if (t >= base && t < base + n) { L = i; }
        base += n;
    }
    base = c_off[L];
    int local = t - base;
    int K3 = c_K3[L], CI = c_CI[L], CO = c_CO[L];
    int k  = local % K3;
    int r  = local / K3;
    int ci = r % CI;
    int co = r / CI;
    wr[base + (ci * K3 + k) * CO + co] = p.w[L][local];
}

// compact active list AND compute mask2 (dilate 3^3 stride2 pad1) in one kernel
__global__ void compact_mask2_kernel(const float* __restrict__ mask, float* __restrict__ mo) {
    int i = blockIdx.x * blockDim.x + threadIdx.x;
    if (i < N1 && mask[i] != 0.0f) {
        int p = atomicAdd(&g_cnt, 1);
        g_list[p] = i;
    }
    if (i < N2) {
        int x = i % W2; int t = i / W2; int y = t % H2; int z = t / H2;
        float mx = 0.0f;
        #pragma unroll
        for (int kz = 0; kz < 3; kz++) {
            int zi = z * 2 - 1 + kz; if ((unsigned)zi >= (unsigned)D1) continue;
            #pragma unroll
            for (int ky = 0; ky < 3; ky++) {
                int yi = y * 2 - 1 + ky; if ((unsigned)yi >= (unsigned)H1) continue;
                #pragma unroll
                for (int kx = 0; kx < 3; kx++) {
                    int xi = x * 2 - 1 + kx; if ((unsigned)xi >= (unsigned)W1) continue;
                    mx = fmaxf(mx, mask[(zi * H1 + yi) * W1 + xi]);
                }
            }
        }
        mo[i] = (mx > 0.0f) ? 1.0f : 0.0f;
    }
}

__global__ void mask_pool_kernel(const float* __restrict__ mi, float* __restrict__ mo,
                                 int ID, int IH, int IW, int OD, int OH, int OW,
                                 int KD, int KH, int KW, int SD, int SH, int SW,
                                 int PD, int PH, int PW) {
    int o = blockIdx.x * blockDim.x + threadIdx.x;
    int n = OD * OH * OW;
    if (o >= n) return;
    int x = o % OW; int t = o / OW; int y = t % OH; int z = t / OH;
    float mx = 0.0f;
    for (int kz = 0; kz < KD; kz++) {
        int zi = z * SD - PD + kz; if ((unsigned)zi >= (unsigned)ID) continue;
        for (int ky = 0; ky < KH; ky++) {
            int yi = y * SH - PH + ky; if ((unsigned)yi >= (unsigned)IH) continue;
            for (int kx = 0; kx < KW; kx++) {
                int xi = x * SW - PW + kx; if ((unsigned)xi >= (unsigned)IW) continue;
                mx = fmaxf(mx, mi[(zi * IH + yi) * IW + xi]);
            }
        }
    }
    mo[o] = (mx > 0.0f) ? 1.0f : 0.0f;
}

// ---------------- sparse gather subm conv with TAP SKIP (3x3x3, s1, p1) ----------------
template<int CI, int CO>
__global__ void subm_gather_kernel(const float* __restrict__ in, const float* __restrict__ mask,
                                   const float* __restrict__ wr, const float* __restrict__ bn,
                                   float* __restrict__ out, int D, int H, int W) {
    const int q = threadIdx.x;       // [0, CO/4)
    const int n = g_cnt;
    const int DHW = D * H * W;
    for (int e = blockIdx.x * blockDim.y + threadIdx.y; e < n; e += gridDim.x * blockDim.y) {
        const int idx = g_list[e];
        const int x  = idx % W;
        const int zy = idx / W;
        const int y  = zy % H;
        const int z  = zy / H;

        float acc[4] = {0.f, 0.f, 0.f, 0.f};
        #pragma unroll
        for (int kz = 0; kz < 3; kz++) {
            int zi = z - 1 + kz; if ((unsigned)zi >= (unsigned)D) continue;
            #pragma unroll
            for (int ky = 0; ky < 3; ky++) {
                int yi = y - 1 + ky; if ((unsigned)yi >= (unsigned)H) continue;
                const int rowb = (zi * H + yi) * W + x;
                #pragma unroll
                for (int kx = 0; kx < 3; kx++) {
                    int xi = x - 1 + kx;
                    if ((unsigned)xi >= (unsigned)W) continue;
                    if (__ldg(mask + rowb + kx - 1) == 0.0f) continue;   // tap skip
                    const float* __restrict__ ptap = in + rowb + kx - 1;
                    const float* __restrict__ wtap =
                        wr + ((kz * 3 + ky) * 3 + kx) * CO + 4 * q;
                    #pragma unroll
                    for (int ci = 0; ci < CI; ci++) {
                        float iv = __ldg(ptap + ci * DHW);
                        float4 w4 = *reinterpret_cast<const float4*>(wtap + ci * 27 * CO);
                        acc[0] += iv * w4.x;
                        acc[1] += iv * w4.y;
                        acc[2] += iv * w4.z;
                        acc[3] += iv * w4.w;
                    }
                }
            }
        }
        #pragma unroll
        for (int j = 0; j < 4; j++) {
            int co = 4 * q + j;
            float g  = bn[co];
            float b  = bn[CO + co];
            float mu = bn[2 * CO + co];
            float vr = bn[3 * CO + co];
            float sc = g * rsqrtf(vr + 1e-3f);
            float sh = b - mu * sc;
            float val = fmaxf(acc[j] * sc + sh, 0.0f);
            out[((co * D + z) * (long)H + y) * W + x] = val;
        }
    }
}

// ---------------- dense conv: 2-CI cp.async pipeline + f32x2 + LDS.64 ----------------
// block = (CO/4, OWT/V, YB); SMW padded even so smem rows allow float2 loads.
template<int CI, int CO, int V, int YB, int OWT, int NT,
         int KD, int KH, int KW, int SD, int SH, int SW, int PD, int PH, int PW>
__global__ void __launch_bounds__(NT, 2)
conv_smem_kernel(const float* __restrict__ in, const float* __restrict__ wr,
                 const float* __restrict__ bn, const float* __restrict__ omask,
                 float* __restrict__ out,
                 int ID, int IH, int IW, int OD, int OH, int OW) {
    constexpr int NSEG    = (V - 1) * SW + KW;
    constexpr int SMH     = (YB - 1) * SH + KH;
    constexpr int SMW_RAW = (OWT - 1) * SW + KW;
    constexpr int SMW     = SMW_RAW + (SMW_RAW & 1);      // pad to even
    constexpr int SMTOT   = KD * SMH * SMW;
    constexpr int NLOAD   = (SMTOT + NT - 1) / NT;
    constexpr int NS      = CI / 2;

    __shared__ __align__(16) float sm[2][2 * SMTOT];

    const int q   = threadIdx.x;
    const int tz  = threadIdx.z;
    const int x0  = threadIdx.y * V;
    const int y   = blockIdx.y * YB + tz;
    const int z   = blockIdx.z;
    const int tid = threadIdx.x + blockDim.x * (threadIdx.y + blockDim.y * threadIdx.z);

    const bool active = (y < OH);
    const int CIstride = ID * IH * IW;

    for (int i = tid; i < 4 * SMTOT; i += NT)
        (&sm[0][0])[i] = 0.0f;

    const int zi_base = z * SD - PD;
    const int yi_base = blockIdx.y * YB * SH - PH;
    int goff[NLOAD];
    unsigned vm = 0;
    #pragma unroll
    for (int j = 0; j < NLOAD; j++) {
        int i  = tid + j * NT;
        int s  = i % SMW;
        int t2 = i / SMW;
        int r  = t2 % SMH;
        int kz = t2 / SMH;
        int zi = zi_base + kz;
        int yi = yi_base + r;
        int xi = s - PW;
        bool ok = (i < SMTOT) && (s < SMW_RAW) && ((unsigned)zi < (unsigned)ID) &&
                  ((unsigned)yi < (unsigned)IH) && ((unsigned)xi < (unsigned)IW);
        goff[j] = ok ? ((zi * IH + yi) * IW + xi) : 0;
        if (ok) vm |= (1u << j);
    }
    __syncthreads();

    float m[V];
    float msum = 0.0f;
    if (active) {
        const int obase = (z * OH + y) * OW;
        #pragma unroll
        for (int v = 0; v < V; v++) {
            m[v] = (x0 + v < OW) ? omask[obase + x0 + v] : 0.0f;
            msum += m[v];
        }
    } else {
        #pragma unroll
        for (int v = 0; v < V; v++) m[v] = 0.0f;
    }
    const bool any = active && (msum > 0.0f);

    ull acc[V][2];
    #pragma unroll
    for (int v = 0; v < V; v++) { acc[v][0] = 0ull; acc[v][1] = 0ull; }

    auto load2 = [&](int ci0, int b) {
        const float* __restrict__ base0 = in + (long)ci0 * CIstride;
        #pragma unroll
        for (int j = 0; j < NLOAD; j++)
            if (vm & (1u << j)) cp4(&sm[b][tid + j * NT], base0 + goff[j]);
        #pragma unroll
        for (int j = 0; j < NLOAD; j++)
            if (vm & (1u << j)) cp4(&sm[b][SMTOT + tid + j * NT], base0 + CIstride + goff[j]);
    };

    load2(0, 0);
    CP_COMMIT();

    for (int st = 0; st < NS; st++) {
        if (st + 1 < NS) load2(2 * (st + 1), (st + 1) & 1);
        CP_COMMIT();
        CP_WAIT1();
        __syncthreads();

        if (any) {
            #pragma unroll
            for (int cc = 0; cc < 2; cc++) {
                const float* __restrict__ smb = &sm[st & 1][cc * SMTOT];
                const float* __restrict__ wci =
                    wr + (2 * st + cc) * (KD * KH * KW * CO) + 4 * q;
                #pragma unroll
                for (int kz = 0; kz < KD; kz++) {
                    #pragma unroll
                    for (int ky = 0; ky < KH; ky++) {
                        const float* __restrict__ row =
                            smb + ((kz * SMH) + tz * SH + ky) * SMW + x0 * SW;
                        // aligned float2 loads (SMW even, x0*SW even, SMTOT even)
                        ull iv2[NSEG];
                        #pragma unroll
                        for (int s = 0; s + 1 < NSEG; s += 2) {
                            float2 p = *reinterpret_cast<const float2*>(row + s);
                            iv2[s]     = f2_dup(p.x);
                            iv2[s + 1] = f2_dup(p.y);
                        }
                        if constexpr (NSEG & 1)
                            iv2[NSEG - 1] = f2_dup(row[NSEG - 1]);
                        const float* __restrict__ wrow = wci + (kz * KH + ky) * KW * CO;
                        #pragma unroll
                        for (int kx = 0; kx < KW; kx++) {
                            union { float4 f; ull u[2]; } wu;
                            wu.f = *reinterpret_cast<const float4*>(wrow + kx * CO);
                            #pragma unroll
                            for (int v = 0; v < V; v++) {
                                ull iv = iv2[v * SW + kx];
                                FMA_F32X2(acc[v][0], iv, wu.u[0], acc[v][0]);
                                FMA_F32X2(acc[v][1], iv, wu.u[1], acc[v][1]);
                            }
                        }
                    }
                }
            }
        }
        __syncthreads();
    }

    if (active) {
        #pragma unroll
        for (int j = 0; j < 2; j++) {
            int ca = 4 * q + 2 * j, cb = ca + 1;
            float sca = bn[ca] * rsqrtf(bn[3 * CO + ca] + 1e-3f);
            float sha = bn[CO + ca] - bn[2 * CO + ca] * sca;
            float scb = bn[cb] * rsqrtf(bn[3 * CO + cb] + 1e-3f);
            float shb = bn[CO + cb] - bn[2 * CO + cb] * scb;
            #pragma unroll
            for (int v = 0; v < V; v++) {
                int x = x0 + v;
                if (x < OW) {
                    float a0, a1; f2_unpack(acc[v][j], a0, a1);
                    bool act = m[v] > 0.0f;
                    out[((ca * OD + z) * (long)OH + y) * OW + x] =
                        act ? fmaxf(fmaf(a0, sca, sha), 0.0f) : 0.0f;
                    out[((cb * OD + z) * (long)OH + y) * OW + x] =
                        act ? fmaxf(fmaf(a1, scb, shb), 0.0f) : 0.0f;
                }
            }
        }
    }
}

// ---------------- launch ----------------
extern "C" void kernel_launch(void* const* d_in, const int* in_sizes, int n_in,
                              void* d_out, int out_size) {
    const float* x    = (const float*)d_in[0];
    const float* mask = (const float*)d_in[1];
    WPtrs wp;
    const float* B_[12];
    for (int i = 0; i < 12; i++) {
        wp.w[i] = (const float*)d_in[2 + 2 * i];
        B_[i]   = (const float*)d_in[3 + 2 * i];
    }
    float* out = (float*)d_out;

    float *bufA, *bufB, *wr, *m2, *m3, *m4, *m5;
    cudaGetSymbolAddress((void**)&bufA, g_bufA);
    cudaGetSymbolAddress((void**)&bufB, g_bufB);
    cudaGetSymbolAddress((void**)&wr,   g_wr);
    cudaGetSymbolAddress((void**)&m2,   g_mask2);
    cudaGetSymbolAddress((void**)&m3,   g_mask3);
    cudaGetSymbolAddress((void**)&m4,   g_mask4);
    cudaGetSymbolAddress((void**)&m5,   g_mask5);

    static const int off[12] = {0, 1728, 8640, 22464, 50112, 77760, 133056,
                                243648, 354240, 464832, 575424, 686016};

    // launch 0: weights reorder + zero bufB + zero g_cnt ; launch 1: compact+mask2
    prep_w_all<<<2776, 256>>>(wp, wr, (float4*)bufB);
    compact_mask2_kernel<<<(N1 + 255) / 256, 256>>>(mask, m2);

    // launch 2,3: gather subm with tap skip
    subm_gather_kernel<4, 16><<<1024, dim3(4, 32)>>>(x, mask, wr + off[0], B_[0], bufA, D1, H1, W1);
    subm_gather_kernel<16, 16><<<1024, dim3(4, 32)>>>(bufA, mask, wr + off[1], B_[1], bufB, D1, H1, W1);

    // launch 4: L2 ; launch 5: L3
    conv_smem_kernel<16, 32, 4, 2, 88, 352, 3, 3, 3, 2, 2, 2, 1, 1, 1>
        <<<dim3(1, H2 / 2, D2), dim3(8, 22, 2)>>>(bufB, wr + off[2], B_[2], m2, bufA,
                                                  D1, H1, W1, D2, H2, W2);
    // L3,L4: V=8, YB=4, block (8,11,4)=352, grid (1,25,21)=525
    conv_smem_kernel<32, 32, 8, 4, 88, 352, 3, 3, 3, 1, 1, 1, 1, 1, 1>
        <<<dim3(1, H2 / 4, D2), dim3(8, 11, 4)>>>(bufA, wr + off[3], B_[3], m2, bufB,
                                                  D2, H2, W2, D2, H2, W2);
    conv_smem_kernel<32, 32, 8, 4, 88, 352, 3, 3, 3, 1, 1, 1, 1, 1, 1>
        <<<dim3(1, H2 / 4, D2), dim3(8, 11, 4)>>>(bufB, wr + off[4], B_[4], m2, bufA,
                                                  D2, H2, W2, D2, H2, W2);

    mask_pool_kernel<<<(N3 + 255) / 256, 256>>>(m2, m3, D2, H2, W2, D3, H3, W3,
                                                3, 3, 3, 2, 2, 2, 1, 1, 1);
    conv_smem_kernel<32, 64, 4, 2, 44, 352, 3, 3, 3, 2, 2, 2, 1, 1, 1>
        <<<dim3(1, H3 / 2, D3), dim3(16, 11, 2)>>>(bufA, wr + off[5], B_[5], m3, bufB,
                                                   D2, H2, W2, D3, H3, W3);
    conv_smem_kernel<64, 64, 4, 2, 44, 352, 3, 3, 3, 1, 1, 1, 1, 1, 1>
        <<<dim3(1, H3 / 2, D3), dim3(16, 11, 2)>>>(bufB, wr + off[6], B_[6], m3, bufA,
                                                   D3, H3, W3, D3, H3, W3);
    conv_smem_kernel<64, 64, 4, 2, 44, 352, 3, 3, 3, 1, 1, 1, 1, 1, 1>
        <<<dim3(1, H3 / 2, D3), dim3(16, 11, 2)>>>(bufA, wr + off[7], B_[7], m3, bufB,
                                                   D3, H3, W3, D3, H3, W3);

    mask_pool_kernel<<<(N4 + 255) / 256, 256>>>(m3, m4, D3, H3, W3, D4, H4, W4,
                                                3, 3, 3, 2, 2, 2, 0, 1, 1);
    conv_smem_kernel<64, 64, 2, 1, 22, 176, 3, 3, 3, 2, 2, 2, 0, 1, 1>
        <<<dim3(1, H4, D4), dim3(16, 11, 1)>>>(bufB, wr + off[8], B_[8], m4, bufA,
                                               D3, H3, W3, D4, H4, W4);
    conv_smem_kernel<64, 64, 2, 1, 22, 176, 3, 3, 3, 1, 1, 1, 1, 1, 1>
        <<<dim3(1, H4, D4), dim3(16, 11, 1)>>>(bufA, wr + off[9], B_[9], m4, bufB,
                                               D4, H4, W4, D4, H4, W4);
    conv_smem_kernel<64, 64, 2, 1, 22, 176, 3, 3, 3, 1, 1, 1, 1, 1, 1>
        <<<dim3(1, H4, D4), dim3(16, 11, 1)>>>(bufB, wr + off[10], B_[10], m4, bufA,
                                               D4, H4, W4, D4, H4, W4);

    mask_pool_kernel<<<(N5 + 255) / 256, 256>>>(m4, m5, D4, H4, W4, D5, H5, W5,
                                                3, 1, 1, 2, 1, 1, 0, 0, 0);
    conv_smem_kernel<64, 128, 2, 1, 22, 352, 3, 1, 1, 2, 1, 1, 0, 0, 0>
        <<<dim3(1, H5, D5), dim3(32, 11, 1)>>>(bufA, wr + off[11], B_[11], m5, out,
                                               D4, H4, W4, D5, H5, W5);
}

// round 15
// speedup vs baseline: 1.9905x; 1.0043x over previous
#include <cuda_runtime.h>

typedef unsigned long long ull;

// ---------------- problem dimensions ----------------
static constexpr int D1=41, H1=200, W1=176; static constexpr int N1=D1*H1*W1;   // 1,443,200
static constexpr int D2=21, H2=100, W2=88;  static constexpr int N2=D2*H2*W2;   // 184,800
static constexpr int D3=11, H3=50,  W3=44;  static constexpr int N3=D3*H3*W3;   // 24,200
static constexpr int D4=5,  H4=25,  W4=22;  static constexpr int N4=D4*H4*W4;   // 2,750
static constexpr int D5=2,  H5=25,  W5=22;  static constexpr int N5=D5*H5*W5;   // 1,100

// ---------------- static device scratch ----------------
__device__ __align__(16) float g_bufA[16 * N1];   // 92.4 MB ping
__device__ __align__(16) float g_bufB[16 * N1];   // 92.4 MB pong
__device__ float g_mask2[N2];
__device__ float g_mask3[N3];
__device__ float g_mask4[N4];
__device__ float g_mask5[N5];
__device__ __align__(16) float g_wr[710592];      // reordered weights, all 12 layers
__device__ int   g_list[N1];
__device__ int   g_cnt;

// weight region metadata (floats)
__device__ __constant__ int c_off[12] = {0, 1728, 8640, 22464, 50112, 77760, 133056,
                                         243648, 354240, 464832, 575424, 686016};
__device__ __constant__ int c_CI[12] = {4, 16, 16, 32, 32, 32, 64, 64, 64, 64, 64, 64};
__device__ __constant__ int c_CO[12] = {16, 16, 32, 32, 32, 64, 64, 64, 64, 64, 64, 128};
__device__ __constant__ int c_K3[12] = {27, 27, 27, 27, 27, 27, 27, 27, 27, 27, 27, 3};

struct WPtrs { const float* w[12]; };

// ---------------- f32x2 + cp.async helpers ----------------
__device__ __forceinline__ ull f2_dup(float v) {
    ull r; asm("mov.b64 %0, {%1, %1};" : "=l"(r) : "f"(v)); return r;
}
__device__ __forceinline__ void f2_unpack(ull v, float& lo, float& hi) {
    asm("mov.b64 {%0, %1}, %2;" : "=f"(lo), "=f"(hi) : "l"(v));
}
#define FMA_F32X2(d, a, b, c) \
    asm("fma.rn.f32x2 %0, %1, %2, %3;" : "=l"(d) : "l"(a), "l"(b), "l"(c))

__device__ __forceinline__ void cp4(float* dst, const float* src) {
    unsigned d = (unsigned)__cvta_generic_to_shared(dst);
    asm volatile("cp.async.ca.shared.global [%0], [%1], 4;" :: "r"(d), "l"(src));
}
#define CP_COMMIT() asm volatile("cp.async.commit_group;" ::: "memory")
#define CP_WAIT1()  asm volatile("cp.async.wait_group 1;"  ::: "memory")

// ---------------- mask box probe (early exit) ----------------
__device__ __forceinline__ float probe_box(const float* __restrict__ mask,
                                           int z0, int z1, int y0, int y1,
                                           int x0, int x1) {
    z0 = max(z0, 0); y0 = max(y0, 0); x0 = max(x0, 0);
    z1 = min(z1, D1 - 1); y1 = min(y1, H1 - 1); x1 = min(x1, W1 - 1);
    for (int z = z0; z <= z1; z++)
        for (int y = y0; y <= y1; y++)
            for (int x = x0; x <= x1; x++)
                if (__ldg(mask + (z * H1 + y) * W1 + x) != 0.0f) return 1.0f;
    return 0.0f;
}

// ---------------- mega prelude: weights + zero bufB + compact + all masks ----------------
// g_cnt must be zeroed by cudaMemsetAsync BEFORE this kernel.
__global__ void prelude_kernel(WPtrs p, const float* __restrict__ mask,
                               float* __restrict__ wr, float4* __restrict__ zb,
                               float* __restrict__ m2o, float* __restrict__ m3o,
                               float* __restrict__ m4o, float* __restrict__ m5o) {
    int t  = blockIdx.x * blockDim.x + threadIdx.x;
    int nt = gridDim.x * blockDim.x;

    // zero bufB (16*N1 floats)
    const int NZ4 = (16 * N1) / 4;
    for (int i = t; i < NZ4; i += nt)
        zb[i] = make_float4(0.f, 0.f, 0.f, 0.f);

    // compact active list
    if (t < N1 && mask[t] != 0.0f) {
        int q = atomicAdd(&g_cnt, 1);
        g_list[q] = t;
    }

    // weight reorder: w [CO][CI][K3] -> wr [CI*K3 + k][CO]
    if (t < 710592) {
        int L = 0, base = 0;
        #pragma unroll
        for (int i = 0; i < 12; i++) {
            int n = c_CO[i] * c_CI[i] * c_K3[i];
            if (t >= base && t < base + n) { L = i; }
            base += n;
        }
        base = c_off[L];
        int local = t - base;
        int K3 = c_K3[L], CI = c_CI[L], CO = c_CO[L];
        int k  = local % K3;
        int r  = local / K3;
        int ci = r % CI;
        int co = r / CI;
        wr[base + (ci * K3 + k) * CO + co] = p.w[L][local];
    }

    // masks: each level expressed directly as a box probe of the base mask.
    if (t < N2) {
        int x = t % W2; int r = t / W2; int y = r % H2; int z = r / H2;
        m2o[t] = probe_box(mask, 2*z-1, 2*z+1, 2*y-1, 2*y+1, 2*x-1, 2*x+1);
    }
    if (t < N3) {
        int x = t % W3; int r = t / W3; int y = r % H3; int z = r / H3;
        m3o[t] = probe_box(mask, 4*z-3, 4*z+3, 4*y-3, 4*y+3, 4*x-3, 4*x+3);
    }
    if (t < N4) {
        int x = t % W4; int r = t / W4; int y = r % H4; int z = r / H4;
        m4o[t] = probe_box(mask, 8*z-3, 8*z+11, 8*y-7, 8*y+7, 8*x-7, 8*x+7);
    }
    if (t < N5) {
        int x = t % W5; int r = t / W5; int y = r % H5; int z = r / H5;
        m5o[t] = probe_box(mask, 16*z-3, 16*z+27, 8*y-7, 8*y+7, 8*x-7, 8*x+7);
    }
}

// ---------------- sparse gather subm conv with TAP SKIP (3x3x3, s1, p1) ----------------
template<int CI, int CO>
__global__ void subm_gather_kernel(const float* __restrict__ in, const float* __restrict__ mask,
                                   const float* __restrict__ wr, const float* __restrict__ bn,
                                   float* __restrict__ out, int D, int H, int W) {
    const int q = threadIdx.x;       // [0, CO/4)
    const int n = g_cnt;
    const int DHW = D * H * W;
    for (int e = blockIdx.x * blockDim.y + threadIdx.y; e < n; e += gridDim.x * blockDim.y) {
        const int idx = g_list[e];
        const int x  = idx % W;
        const int zy = idx / W;
        const int y  = zy % H;
        const int z  = zy / H;

        float acc[4] = {0.f, 0.f, 0.f, 0.f};
        #pragma unroll
        for (int kz = 0; kz < 3; kz++) {
            int zi = z - 1 + kz; if ((unsigned)zi >= (unsigned)D) continue;
            #pragma unroll
            for (int ky = 0; ky < 3; ky++) {
                int yi = y - 1 + ky; if ((unsigned)yi >= (unsigned)H) continue;
                const int rowb = (zi * H + yi) * W + x;
                #pragma unroll
                for (int kx = 0; kx < 3; kx++) {
                    int xi = x - 1 + kx;
                    if ((unsigned)xi >= (unsigned)W) continue;
                    if (__ldg(mask + rowb + kx - 1) == 0.0f) continue;   // tap skip
                    const float* __restrict__ ptap = in + rowb + kx - 1;
                    const float* __restrict__ wtap =
                        wr + ((kz * 3 + ky) * 3 + kx) * CO + 4 * q;
                    #pragma unroll
                    for (int ci = 0; ci < CI; ci++) {
                        float iv = __ldg(ptap + ci * DHW);
                        float4 w4 = *reinterpret_cast<const float4*>(wtap + ci * 27 * CO);
                        acc[0] += iv * w4.x;
                        acc[1] += iv * w4.y;
                        acc[2] += iv * w4.z;
                        acc[3] += iv * w4.w;
                    }
                }
            }
        }
        #pragma unroll
        for (int j = 0; j < 4; j++) {
            int co = 4 * q + j;
            float g  = bn[co];
            float b  = bn[CO + co];
            float mu = bn[2 * CO + co];
            float vr = bn[3 * CO + co];
            float sc = g * rsqrtf(vr + 1e-3f);
            float sh = b - mu * sc;
            float val = fmaxf(acc[j] * sc + sh, 0.0f);
            out[((co * D + z) * (long)H + y) * W + x] = val;
        }
    }
}

// ---------------- dense conv: CIPS-CI cp.async pipeline + f32x2 + LDS.64 ----------------
// block = (CO/4, OWT/V, YB); SMW padded even for aligned float2 smem loads.
template<int CI, int CO, int CIPS, int V, int YB, int OWT, int NT,
         int KD, int KH, int KW, int SD, int SH, int SW, int PD, int PH, int PW>
__global__ void __launch_bounds__(NT, 2)
conv_smem_kernel(const float* __restrict__ in, const float* __restrict__ wr,
                 const float* __restrict__ bn, const float* __restrict__ omask,
                 float* __restrict__ out,
                 int ID, int IH, int IW, int OD, int OH, int OW) {
    constexpr int NSEG    = (V - 1) * SW + KW;
    constexpr int SMH     = (YB - 1) * SH + KH;
    constexpr int SMW_RAW = (OWT - 1) * SW + KW;
    constexpr int SMW     = SMW_RAW + (SMW_RAW & 1);      // pad to even
    constexpr int SMTOT   = KD * SMH * SMW;
    constexpr int NLOAD   = (SMTOT + NT - 1) / NT;
    constexpr int NS      = CI / CIPS;

    __shared__ __align__(16) float sm[2][CIPS * SMTOT];

    const int q   = threadIdx.x;
    const int tz  = threadIdx.z;
    const int x0  = threadIdx.y * V;
    const int y   = blockIdx.y * YB + tz;
    const int z   = blockIdx.z;
    const int tid = threadIdx.x + blockDim.x * (threadIdx.y + blockDim.y * threadIdx.z);

    const bool active = (y < OH);
    const int CIstride = ID * IH * IW;

    for (int i = tid; i < 2 * CIPS * SMTOT; i += NT)
        (&sm[0][0])[i] = 0.0f;

    const int zi_base = z * SD - PD;
    const int yi_base = blockIdx.y * YB * SH - PH;
    int goff[NLOAD];
    unsigned vm = 0;
    #pragma unroll
    for (int j = 0; j < NLOAD; j++) {
        int i  = tid + j * NT;
        int s  = i % SMW;
        int t2 = i / SMW;
        int r  = t2 % SMH;
        int kz = t2 / SMH;
        int zi = zi_base + kz;
        int yi = yi_base + r;
        int xi = s - PW;
        bool ok = (i < SMTOT) && (s < SMW_RAW) && ((unsigned)zi < (unsigned)ID) &&
                  ((unsigned)yi < (unsigned)IH) && ((unsigned)xi < (unsigned)IW);
        goff[j] = ok ? ((zi * IH + yi) * IW + xi) : 0;
        if (ok) vm |= (1u << j);
    }
    __syncthreads();

    float m[V];
    float msum = 0.0f;
    if (active) {
        const int obase = (z * OH + y) * OW;
        #pragma unroll
        for (int v = 0; v < V; v++) {
            m[v] = (x0 + v < OW) ? omask[obase + x0 + v] : 0.0f;
            msum += m[v];
        }
    } else {
        #pragma unroll
        for (int v = 0; v < V; v++) m[v] = 0.0f;
    }
    const bool any = active && (msum > 0.0f);

    ull acc[V][2];
    #pragma unroll
    for (int v = 0; v < V; v++) { acc[v][0] = 0ull; acc[v][1] = 0ull; }

    auto loadg = [&](int ci0, int b) {
        #pragma unroll
        for (int g = 0; g < CIPS; g++) {
            const float* __restrict__ base0 = in + (long)(ci0 + g) * CIstride;
            #pragma unroll
            for (int j = 0; j < NLOAD; j++)
                if (vm & (1u << j)) cp4(&sm[b][g * SMTOT + tid + j * NT], base0 + goff[j]);
        }
    };

    loadg(0, 0);
    CP_COMMIT();

    for (int st = 0; st < NS; st++) {
        if (st + 1 < NS) loadg((st + 1) * CIPS, (st + 1) & 1);
        CP_COMMIT();
        CP_WAIT1();
        __syncthreads();

        if (any) {
            #pragma unroll 2
            for (int cc = 0; cc < CIPS; cc++) {
                const float* __restrict__ smb = &sm[st & 1][cc * SMTOT];
                const float* __restrict__ wci =
                    wr + (st * CIPS + cc) * (KD * KH * KW * CO) + 4 * q;
                #pragma unroll
                for (int kz = 0; kz < KD; kz++) {
                    #pragma unroll
                    for (int ky = 0; ky < KH; ky++) {
                        const float* __restrict__ row =
                            smb + ((kz * SMH) + tz * SH + ky) * SMW + x0 * SW;
                        ull iv2[NSEG];
                        #pragma unroll
                        for (int s = 0; s + 1 < NSEG; s += 2) {
                            float2 pp = *reinterpret_cast<const float2*>(row + s);
                            iv2[s]     = f2_dup(pp.x);
                            iv2[s + 1] = f2_dup(pp.y);
                        }
                        if constexpr (NSEG & 1)
                            iv2[NSEG - 1] = f2_dup(row[NSEG - 1]);
                        const float* __restrict__ wrow = wci + (kz * KH + ky) * KW * CO;
                        #pragma unroll
                        for (int kx = 0; kx < KW; kx++) {
                            union { float4 f; ull u[2]; } wu;
                            wu.f = *reinterpret_cast<const float4*>(wrow + kx * CO);
                            #pragma unroll
                            for (int v = 0; v < V; v++) {
                                ull iv = iv2[v * SW + kx];
                                FMA_F32X2(acc[v][0], iv, wu.u[0], acc[v][0]);
                                FMA_F32X2(acc[v][1], iv, wu.u[1], acc[v][1]);
                            }
                        }
                    }
                }
            }
        }
        __syncthreads();
    }

    if (active) {
        #pragma unroll
        for (int j = 0; j < 2; j++) {
            int ca = 4 * q + 2 * j, cb = ca + 1;
            float sca = bn[ca] * rsqrtf(bn[3 * CO + ca] + 1e-3f);
            float sha = bn[CO + ca] - bn[2 * CO + ca] * sca;
            float scb = bn[cb] * rsqrtf(bn[3 * CO + cb] + 1e-3f);
            float shb = bn[CO + cb] - bn[2 * CO + cb] * scb;
            #pragma unroll
            for (int v = 0; v < V; v++) {
                int x = x0 + v;
                if (x < OW) {
                    float a0, a1; f2_unpack(acc[v][j], a0, a1);
                    bool act = m[v] > 0.0f;
                    out[((ca * OD + z) * (long)OH + y) * OW + x] =
                        act ? fmaxf(fmaf(a0, sca, sha), 0.0f) : 0.0f;
                    out[((cb * OD + z) * (long)OH + y) * OW + x] =
                        act ? fmaxf(fmaf(a1, scb, shb), 0.0f) : 0.0f;
                }
            }
        }
    }
}

// ---------------- launch ----------------
extern "C" void kernel_launch(void* const* d_in, const int* in_sizes, int n_in,
                              void* d_out, int out_size) {
    const float* x    = (const float*)d_in[0];
    const float* mask = (const float*)d_in[1];
    WPtrs wp;
    const float* B_[12];
    for (int i = 0; i < 12; i++) {
        wp.w[i] = (const float*)d_in[2 + 2 * i];
        B_[i]   = (const float*)d_in[3 + 2 * i];
    }
    float* out = (float*)d_out;

    float *bufA, *bufB, *wr, *m2, *m3, *m4, *m5;
    int* cntp;
    cudaGetSymbolAddress((void**)&bufA, g_bufA);
    cudaGetSymbolAddress((void**)&bufB, g_bufB);
    cudaGetSymbolAddress((void**)&wr,   g_wr);
    cudaGetSymbolAddress((void**)&m2,   g_mask2);
    cudaGetSymbolAddress((void**)&m3,   g_mask3);
    cudaGetSymbolAddress((void**)&m4,   g_mask4);
    cudaGetSymbolAddress((void**)&m5,   g_mask5);
    cudaGetSymbolAddress((void**)&cntp, g_cnt);

    static const int off[12] = {0, 1728, 8640, 22464, 50112, 77760, 133056,
                                243648, 354240, 464832, 575424, 686016};

    cudaMemsetAsync(cntp, 0, sizeof(int), 0);   // DMA fill, not a kernel launch

    // kernel 0: mega-prelude (weights + zero bufB + compact + m2..m5)
    prelude_kernel<<<(N1 + 255) / 256, 256>>>(wp, mask, wr, (float4*)bufB, m2, m3, m4, m5);

    // kernels 1,2: gather subm with tap skip
    subm_gather_kernel<4, 16><<<1024, dim3(4, 32)>>>(x, mask, wr + off[0], B_[0], bufA, D1, H1, W1);
    subm_gather_kernel<16, 16><<<1024, dim3(4, 32)>>>(bufA, mask, wr + off[1], B_[1], bufB, D1, H1, W1);

    // kernel 3: L2  <-- ncu capture lands here
    conv_smem_kernel<16, 32, 2, 4, 2, 88, 352, 3, 3, 3, 2, 2, 2, 1, 1, 1>
        <<<dim3(1, H2 / 2, D2), dim3(8, 22, 2)>>>(bufB, wr + off[2], B_[2], m2, bufA,
                                                  D1, H1, W1, D2, H2, W2);
    // L3,L4: V=8, YB=4 (unchanged structure, CIPS=2)
    conv_smem_kernel<32, 32, 2, 8, 4, 88, 352, 3, 3, 3, 1, 1, 1, 1, 1, 1>
        <<<dim3(1, H2 / 4, D2), dim3(8, 11, 4)>>>(bufA, wr + off[3], B_[3], m2, bufB,
                                                  D2, H2, W2, D2, H2, W2);
    conv_smem_kernel<32, 32, 2, 8, 4, 88, 352, 3, 3, 3, 1, 1, 1, 1, 1, 1>
        <<<dim3(1, H2 / 4, D2), dim3(8, 11, 4)>>>(bufB, wr + off[4], B_[4], m2, bufA,
                                                  D2, H2, W2, D2, H2, W2);

    // L5: CIPS=4 (8 pipeline stages instead of 16)
    conv_smem_kernel<32, 64, 4, 4, 2, 44, 352, 3, 3, 3, 2, 2, 2, 1, 1, 1>
        <<<dim3(1, H3 / 2, D3), dim3(16, 11, 2)>>>(bufA, wr + off[5], B_[5], m3, bufB,
                                                   D2, H2, W2, D3, H3, W3);
    // L6,L7: CIPS=8 (8 stages instead of 32)
    conv_smem_kernel<64, 64, 8, 4, 2, 44, 352, 3, 3, 3, 1, 1, 1, 1, 1, 1>
        <<<dim3(1, H3 / 2, D3), dim3(16, 11, 2)>>>(bufB, wr + off[6], B_[6], m3, bufA,
                                                   D3, H3, W3, D3, H3, W3);
    conv_smem_kernel<64, 64, 8, 4, 2, 44, 352, 3, 3, 3, 1, 1, 1, 1, 1, 1>
        <<<dim3(1, H3 / 2, D3), dim3(16, 11, 2)>>>(bufA, wr + off[7], B_[7], m3, bufB,
                                                   D3, H3, W3, D3, H3, W3);

    // L8: CIPS=8
    conv_smem_kernel<64, 64, 8, 2, 1, 22, 176, 3, 3, 3, 2, 2, 2, 0, 1, 1>
        <<<dim3(1, H4, D4), dim3(16, 11, 1)>>>(bufB, wr + off[8], B_[8], m4, bufA,
                                               D3, H3, W3, D4, H4, W4);
    // L9,L10: CIPS=8
    conv_smem_kernel<64, 64, 8, 2, 1, 22, 176, 3, 3, 3, 1, 1, 1, 1, 1, 1>
        <<<dim3(1, H4, D4), dim3(16, 11, 1)>>>(bufA, wr + off[9], B_[9], m4, bufB,
                                               D4, H4, W4, D4, H4, W4);
    conv_smem_kernel<64, 64, 8, 2, 1, 22, 176, 3, 3, 3, 1, 1, 1, 1, 1, 1>
        <<<dim3(1, H4, D4), dim3(16, 11, 1)>>>(bufB, wr + off[10], B_[10], m4, bufA,
                                               D4, H4, W4, D4, H4, W4);

    // L11: CIPS=16 (4 stages)
    conv_smem_kernel<64, 128, 16, 2, 1, 22, 352, 3, 1, 1, 2, 1, 1, 0, 0, 0>
        <<<dim3(1, H5, D5), dim3(32, 11, 1)>>>(bufA, wr + off[11], B_[11], m5, out,
                                               D4, H4, W4, D5, H5, W5);
}